// round 7
// baseline (speedup 1.0000x reference)
#include <cuda_runtime.h>
#include <cuda_bf16.h>
#include <math.h>
#include <stdint.h>

// Problem constants
#define BATCH 2
#define SEQ   2048
#define DM    1024
#define NH    16
#define DH    64
#define DFF   512
#define ROWS  (BATCH*SEQ)          // 4096

// ---------------- scratch (device globals; no runtime allocation) ----------
__device__ float g_xn[ROWS*DM];    // norm1(x)
__device__ float g_q [ROWS*DM];
__device__ float g_k [ROWS*DM];
__device__ float g_v [ROWS*DM];
__device__ float g_vt[ROWS*DM];    // V transposed per head: [b*16+h][d][s]
__device__ float g_ao[ROWS*DM];    // attention output (pre-Wo)
__device__ float g_x2[ROWS*DM];    // x_n + attn@Wo + bo
__device__ float g_hn[ROWS*DM];    // norm2(x2)
__device__ float g_h1[ROWS*DFF];   // relu(hn@W1+b1)

// ---------------- helpers ---------------------------------------------------
__device__ __forceinline__ float to_tf32(float x) {
    float r;
    asm("cvt.rna.tf32.f32 %0, %1;" : "=f"(r) : "f"(x));
    return r;
}

__device__ __forceinline__ void mma_tf32(float c[4],
                                         uint32_t a0, uint32_t a1, uint32_t a2, uint32_t a3,
                                         uint32_t b0, uint32_t b1) {
    asm volatile(
        "mma.sync.aligned.m16n8k8.row.col.f32.tf32.tf32.f32 "
        "{%0,%1,%2,%3}, {%4,%5,%6,%7}, {%8,%9}, {%0,%1,%2,%3};"
        : "+f"(c[0]), "+f"(c[1]), "+f"(c[2]), "+f"(c[3])
        : "r"(a0), "r"(a1), "r"(a2), "r"(a3), "r"(b0), "r"(b1));
}

// ---------------- NormLayer -------------------------------------------------
__global__ __launch_bounds__(256)
void norm_kernel(const float* __restrict__ X,
                 const float* __restrict__ alpha,
                 const float* __restrict__ beta,
                 float* __restrict__ Y)
{
    int row = blockIdx.x;
    int tid = threadIdx.x;
    const float* xr = X + (size_t)row * DM;

    float4 v = *(const float4*)(xr + tid * 4);
    float s  = v.x + v.y + v.z + v.w;
    float sq = v.x*v.x + v.y*v.y + v.z*v.z + v.w*v.w;

    #pragma unroll
    for (int m = 16; m; m >>= 1) {
        s  += __shfl_xor_sync(0xffffffffu, s,  m);
        sq += __shfl_xor_sync(0xffffffffu, sq, m);
    }
    __shared__ float red[16];
    __shared__ float s_mean, s_rstd;
    int wid  = tid >> 5;
    int lane = tid & 31;
    if (lane == 0) { red[wid] = s; red[8 + wid] = sq; }
    __syncthreads();
    if (tid == 0) {
        float S = 0.f, SQ = 0.f;
        #pragma unroll
        for (int w = 0; w < 8; w++) { S += red[w]; SQ += red[8 + w]; }
        float mean = S * (1.0f / DM);
        float var  = (SQ - (float)DM * mean * mean) * (1.0f / (DM - 1));
        s_mean = mean;
        s_rstd = rsqrtf(var + 1e-6f);
    }
    __syncthreads();
    float mean = s_mean, rstd = s_rstd;

    float4 a = *(const float4*)(alpha + tid * 4);
    float4 b = *(const float4*)(beta  + tid * 4);
    float4 o;
    o.x = a.x * (v.x - mean) * rstd + b.x;
    o.y = a.y * (v.y - mean) * rstd + b.y;
    o.z = a.z * (v.z - mean) * rstd + b.z;
    o.w = a.w * (v.w - mean) * rstd + b.w;
    *(float4*)(Y + (size_t)row * DM + tid * 4) = o;
}

// ---------------- V transpose per head: g_v[row][h*64+d] -> g_vt[bh][d][s] --
__global__ __launch_bounds__(256)
void vtrans_kernel(const float* __restrict__ V, float* __restrict__ VT)
{
    __shared__ float ts[64 * 65];
    int tid = threadIdx.x;
    int bh = blockIdx.y;
    int s0 = blockIdx.x * 64;
    size_t base = (size_t)(bh >> 4) * SEQ * DM + (bh & 15) * DH;

    for (int f = tid; f < 64 * 16; f += 256) {
        int s = f >> 4, c4 = (f & 15) << 2;
        float4 v = *(const float4*)(V + base + (size_t)(s0 + s) * DM + c4);
        ts[s * 65 + c4 + 0] = v.x;
        ts[s * 65 + c4 + 1] = v.y;
        ts[s * 65 + c4 + 2] = v.z;
        ts[s * 65 + c4 + 3] = v.w;
    }
    __syncthreads();
    for (int f = tid; f < 64 * 16; f += 256) {
        int d = f >> 4, s4 = (f & 15) << 2;
        float4 w;
        w.x = ts[(s4 + 0) * 65 + d];
        w.y = ts[(s4 + 1) * 65 + d];
        w.z = ts[(s4 + 2) * 65 + d];
        w.w = ts[(s4 + 3) * 65 + d];
        *(float4*)(VT + (size_t)(bh * DH + d) * SEQ + s0 + s4) = w;
    }
}

// ---------------- big tf32 GEMM: 128x256 block, 8 warps, warp 64x64 --------
// sA: [128][24], k-pair-interleaved columns (k -> (k&8)|((k&3)<<1)|((k>>2)&1))
// sB: [16][264], natural [k][n]
#define BSA 24
#define BSB 264
template<bool RELU, bool HAS_RES>
__device__ __forceinline__ void gemm256_body(
    const float* __restrict__ A, const float* __restrict__ B,
    const float* __restrict__ bias, const float* __restrict__ Res,
    float* __restrict__ C, int N, int K, int bm, int bnc, float* sm)
{
    float* sAb[2] = { sm,        sm + 3072 };
    float* sBb[2] = { sm + 6144, sm + 6144 + 4224 };

    int tid  = threadIdx.x;
    int warp = tid >> 5, lane = tid & 31;
    int gid  = lane >> 2, tg = lane & 3;
    int wm   = (warp & 1) * 64;
    int wn   = (warp >> 1) * 64;

    // loader indices
    int ar[2], abc[2];        // A: row, interleaved base col
    int bk[4], bn4[4];        // B: k row, n offset
    #pragma unroll
    for (int i = 0; i < 2; i++) {
        int f = tid + 256 * i;
        ar[i]  = f >> 2;
        int c4 = (f & 3) << 2;              // 0,4,8,12
        abc[i] = (c4 & 8) | ((c4 >> 2) & 1);// 0,1,8,9
    }
    #pragma unroll
    for (int i = 0; i < 4; i++) {
        int f = tid + 256 * i;
        bk[i]  = f >> 6;                    // 0..15
        bn4[i] = (f & 63) << 2;             // 0..252
    }
    const float* Abase = A + (size_t)(bm * 128) * K;
    const float* Bbase = B + bnc;

    int nk = K >> 4;

    // prologue: chunk 0
    #pragma unroll
    for (int i = 0; i < 2; i++) {
        float4 va = *(const float4*)(Abase + (size_t)ar[i] * K + ((tid + 256*i) & 3) * 4);
        int ro = ar[i] * BSA + abc[i];
        sAb[0][ro + 0] = to_tf32(va.x);
        sAb[0][ro + 2] = to_tf32(va.y);
        sAb[0][ro + 4] = to_tf32(va.z);
        sAb[0][ro + 6] = to_tf32(va.w);
    }
    #pragma unroll
    for (int i = 0; i < 4; i++) {
        float4 vb = *(const float4*)(Bbase + (size_t)bk[i] * N + bn4[i]);
        vb.x = to_tf32(vb.x); vb.y = to_tf32(vb.y);
        vb.z = to_tf32(vb.z); vb.w = to_tf32(vb.w);
        *(float4*)&sBb[0][bk[i] * BSB + bn4[i]] = vb;
    }
    __syncthreads();

    float acc[4][8][4];
    #pragma unroll
    for (int mt = 0; mt < 4; mt++)
        #pragma unroll
        for (int nt = 0; nt < 8; nt++)
            #pragma unroll
            for (int r = 0; r < 4; r++) acc[mt][nt][r] = 0.f;

    int cur = 0;
    for (int kt = 0; kt < nk; kt++) {
        float4 va[2], vb[4];
        bool has_next = (kt + 1 < nk);
        if (has_next) {
            int k0 = (kt + 1) << 4;
            #pragma unroll
            for (int i = 0; i < 2; i++)
                va[i] = *(const float4*)(Abase + (size_t)ar[i] * K + k0 + ((tid + 256*i) & 3) * 4);
            #pragma unroll
            for (int i = 0; i < 4; i++)
                vb[i] = *(const float4*)(Bbase + (size_t)(k0 + bk[i]) * N + bn4[i]);
        }

        const float* As = sAb[cur];
        const float* Bs = sBb[cur];
        #pragma unroll
        for (int kk = 0; kk < 16; kk += 8) {
            float2 afl[4][2];
            #pragma unroll
            for (int mt = 0; mt < 4; mt++) {
                int r0 = wm + mt * 16 + gid;
                afl[mt][0] = *(const float2*)&As[r0 * BSA + kk + 2 * tg];
                afl[mt][1] = *(const float2*)&As[(r0 + 8) * BSA + kk + 2 * tg];
            }
            uint32_t b0[8], b1[8];
            #pragma unroll
            for (int nt = 0; nt < 8; nt++) {
                int cc = wn + nt * 8 + gid;
                b0[nt] = __float_as_uint(Bs[(kk + tg) * BSB + cc]);
                b1[nt] = __float_as_uint(Bs[(kk + tg + 4) * BSB + cc]);
            }
            #pragma unroll
            for (int mt = 0; mt < 4; mt++)
                #pragma unroll
                for (int nt = 0; nt < 8; nt++)
                    mma_tf32(acc[mt][nt],
                             __float_as_uint(afl[mt][0].x), __float_as_uint(afl[mt][1].x),
                             __float_as_uint(afl[mt][0].y), __float_as_uint(afl[mt][1].y),
                             b0[nt], b1[nt]);
        }

        if (has_next) {
            int nxt = cur ^ 1;
            #pragma unroll
            for (int i = 0; i < 2; i++) {
                int ro = ar[i] * BSA + abc[i];
                sAb[nxt][ro + 0] = to_tf32(va[i].x);
                sAb[nxt][ro + 2] = to_tf32(va[i].y);
                sAb[nxt][ro + 4] = to_tf32(va[i].z);
                sAb[nxt][ro + 6] = to_tf32(va[i].w);
            }
            #pragma unroll
            for (int i = 0; i < 4; i++) {
                vb[i].x = to_tf32(vb[i].x); vb[i].y = to_tf32(vb[i].y);
                vb[i].z = to_tf32(vb[i].z); vb[i].w = to_tf32(vb[i].w);
                *(float4*)&sBb[nxt][bk[i] * BSB + bn4[i]] = vb[i];
            }
            __syncthreads();
            cur = nxt;
        }
    }

    // epilogue
    #pragma unroll
    for (int nt = 0; nt < 8; nt++) {
        int col = bnc + wn + nt * 8 + 2 * tg;
        float2 bv = *(const float2*)(bias + col);
        #pragma unroll
        for (int mt = 0; mt < 4; mt++) {
            int r0 = bm * 128 + wm + mt * 16 + gid;
            int r1 = r0 + 8;
            float2 c0 = make_float2(acc[mt][nt][0] + bv.x, acc[mt][nt][1] + bv.y);
            float2 c1 = make_float2(acc[mt][nt][2] + bv.x, acc[mt][nt][3] + bv.y);
            if (RELU) {
                c0.x = fmaxf(c0.x, 0.f); c0.y = fmaxf(c0.y, 0.f);
                c1.x = fmaxf(c1.x, 0.f); c1.y = fmaxf(c1.y, 0.f);
            }
            if (HAS_RES) {
                float2 r0v = *(const float2*)(Res + (size_t)r0 * N + col);
                float2 r1v = *(const float2*)(Res + (size_t)r1 * N + col);
                c0.x += r0v.x; c0.y += r0v.y;
                c1.x += r1v.x; c1.y += r1v.y;
            }
            *(float2*)(C + (size_t)r0 * N + col) = c0;
            *(float2*)(C + (size_t)r1 * N + col) = c1;
        }
    }
}

template<bool RELU, bool HAS_RES>
__global__ __launch_bounds__(256)
void tgemm256(const float* __restrict__ A, const float* __restrict__ B,
              const float* __restrict__ bias, const float* __restrict__ Res,
              float* __restrict__ C, int N, int K)
{
    extern __shared__ float smdyn[];
    gemm256_body<RELU, HAS_RES>(A, B, bias, Res, C, N, K,
                                blockIdx.y, blockIdx.x * 256, smdyn);
}

// fused QKV: blockIdx.x in 0..11 -> (weight select, col block)
__global__ __launch_bounds__(256)
void qkv_gemm(const float* __restrict__ A,
              const float* __restrict__ Wq, const float* __restrict__ Wk,
              const float* __restrict__ Wv,
              const float* __restrict__ bq, const float* __restrict__ bk,
              const float* __restrict__ bv,
              float* __restrict__ Oq, float* __restrict__ Ok, float* __restrict__ Ov)
{
    extern __shared__ float smdyn[];
    int sel = blockIdx.x >> 2;
    int bnc = (blockIdx.x & 3) * 256;
    const float* B    = (sel == 0) ? Wq : (sel == 1) ? Wk : Wv;
    const float* bias = (sel == 0) ? bq : (sel == 1) ? bk : bv;
    float* C          = (sel == 0) ? Oq : (sel == 1) ? Ok : Ov;
    gemm256_body<false, false>(A, B, bias, nullptr, C, DM, DM,
                               blockIdx.y, bnc, smdyn);
}

// ---------------- small tf32 GEMM (128x128) for FFN1 -----------------------
#define SA_STR 20
#define SB_STR 136
template<bool RELU, bool HAS_RES>
__global__ __launch_bounds__(256)
void tgemm(const float* __restrict__ A, const float* __restrict__ B,
           const float* __restrict__ bias, const float* __restrict__ Res,
           float* __restrict__ C, int M, int N, int K)
{
    __shared__ float sA[2][128 * SA_STR];
    __shared__ float sB[2][16 * SB_STR];

    int tid  = threadIdx.x;
    int warp = tid >> 5, lane = tid & 31;
    int gid  = lane >> 2, tg = lane & 3;
    int wm   = (warp & 1) * 64;
    int wn   = (warp >> 1) * 32;
    int bm = blockIdx.y, bn = blockIdx.x;

    int am[2], ac4[2], bk[2], bn4[2];
    #pragma unroll
    for (int i = 0; i < 2; i++) {
        int f = tid + 256 * i;
        am[i]  = f >> 2;
        ac4[i] = (f & 3) << 2;
        bk[i]  = f >> 5;
        bn4[i] = (f & 31) << 2;
    }
    const float* Abase = A + (size_t)(bm * 128) * K;
    const float* Bbase = B + bn * 128;

    int nk = K >> 4;

    #pragma unroll
    for (int i = 0; i < 2; i++) {
        float4 va = *(const float4*)(Abase + (size_t)am[i] * K + ac4[i]);
        va.x = to_tf32(va.x); va.y = to_tf32(va.y);
        va.z = to_tf32(va.z); va.w = to_tf32(va.w);
        *(float4*)&sA[0][am[i] * SA_STR + ac4[i]] = va;
        float4 vb = *(const float4*)(Bbase + (size_t)bk[i] * N + bn4[i]);
        vb.x = to_tf32(vb.x); vb.y = to_tf32(vb.y);
        vb.z = to_tf32(vb.z); vb.w = to_tf32(vb.w);
        *(float4*)&sB[0][bk[i] * SB_STR + bn4[i]] = vb;
    }
    __syncthreads();

    float acc[4][4][4];
    #pragma unroll
    for (int mt = 0; mt < 4; mt++)
        #pragma unroll
        for (int nt = 0; nt < 4; nt++)
            #pragma unroll
            for (int r = 0; r < 4; r++) acc[mt][nt][r] = 0.f;

    int cur = 0;
    for (int kt = 0; kt < nk; kt++) {
        float4 va[2], vb[2];
        bool has_next = (kt + 1 < nk);
        if (has_next) {
            int k0 = (kt + 1) << 4;
            #pragma unroll
            for (int i = 0; i < 2; i++) {
                va[i] = *(const float4*)(Abase + (size_t)am[i] * K + k0 + ac4[i]);
                vb[i] = *(const float4*)(Bbase + (size_t)(k0 + bk[i]) * N + bn4[i]);
            }
        }

        const float* As = sA[cur];
        const float* Bs = sB[cur];
        #pragma unroll
        for (int kk = 0; kk < 16; kk += 8) {
            uint32_t af[4][4], bf[4][2];
            #pragma unroll
            for (int mt = 0; mt < 4; mt++) {
                int r0 = (wm + mt * 16 + gid) * SA_STR;
                int r1 = (wm + mt * 16 + gid + 8) * SA_STR;
                af[mt][0] = __float_as_uint(As[r0 + kk + tg]);
                af[mt][1] = __float_as_uint(As[r1 + kk + tg]);
                af[mt][2] = __float_as_uint(As[r0 + kk + tg + 4]);
                af[mt][3] = __float_as_uint(As[r1 + kk + tg + 4]);
            }
            #pragma unroll
            for (int nt = 0; nt < 4; nt++) {
                int cc = wn + nt * 8 + gid;
                bf[nt][0] = __float_as_uint(Bs[(kk + tg) * SB_STR + cc]);
                bf[nt][1] = __float_as_uint(Bs[(kk + tg + 4) * SB_STR + cc]);
            }
            #pragma unroll
            for (int mt = 0; mt < 4; mt++)
                #pragma unroll
                for (int nt = 0; nt < 4; nt++)
                    mma_tf32(acc[mt][nt], af[mt][0], af[mt][1], af[mt][2], af[mt][3],
                             bf[nt][0], bf[nt][1]);
        }

        if (has_next) {
            int nxt = cur ^ 1;
            #pragma unroll
            for (int i = 0; i < 2; i++) {
                va[i].x = to_tf32(va[i].x); va[i].y = to_tf32(va[i].y);
                va[i].z = to_tf32(va[i].z); va[i].w = to_tf32(va[i].w);
                *(float4*)&sA[nxt][am[i] * SA_STR + ac4[i]] = va[i];
                vb[i].x = to_tf32(vb[i].x); vb[i].y = to_tf32(vb[i].y);
                vb[i].z = to_tf32(vb[i].z); vb[i].w = to_tf32(vb[i].w);
                *(float4*)&sB[nxt][bk[i] * SB_STR + bn4[i]] = vb[i];
            }
            __syncthreads();
            cur = nxt;
        }
    }

    #pragma unroll
    for (int nt = 0; nt < 4; nt++) {
        int col = bn * 128 + wn + nt * 8 + 2 * tg;
        float2 bv = *(const float2*)(bias + col);
        #pragma unroll
        for (int mt = 0; mt < 4; mt++) {
            int r0 = bm * 128 + wm + mt * 16 + gid;
            int r1 = r0 + 8;
            float2 c0 = make_float2(acc[mt][nt][0] + bv.x, acc[mt][nt][1] + bv.y);
            float2 c1 = make_float2(acc[mt][nt][2] + bv.x, acc[mt][nt][3] + bv.y);
            if (RELU) {
                c0.x = fmaxf(c0.x, 0.f); c0.y = fmaxf(c0.y, 0.f);
                c1.x = fmaxf(c1.x, 0.f); c1.y = fmaxf(c1.y, 0.f);
            }
            if (HAS_RES) {
                float2 r0v = *(const float2*)(Res + (size_t)r0 * N + col);
                float2 r1v = *(const float2*)(Res + (size_t)r1 * N + col);
                c0.x += r0v.x; c0.y += r0v.y;
                c1.x += r1v.x; c1.y += r1v.y;
            }
            *(float2*)(C + (size_t)r0 * N + col) = c0;
            *(float2*)(C + (size_t)r1 * N + col) = c1;
        }
    }
}

// ---------------- flash attention v2 ---------------------------------------
// 256 threads (8 warps), 128 queries/block, 64-key tiles.
// sK: natural [key][d] stride 72 (B-operand for S, col-major == K itself)
// sVT: [d][key] stride 68 (B-operand for PV), from pre-transposed g_vt
// P never touches smem: C-fragments -> A-fragments via warp shuffles.
#define KSTR 72
#define VSTR 68
__global__ __launch_bounds__(256)
void attn2_kernel(const float* __restrict__ Q, const float* __restrict__ Kb,
                  const float* __restrict__ VT, float* __restrict__ O)
{
    __shared__ float smem[64 * KSTR + 64 * VSTR];   // 8960 floats
    float* sK  = smem;
    float* sVT = smem + 64 * KSTR;
    float* sQ  = smem;                              // staging, stride 70, 128 rows

    int tid  = threadIdx.x;
    int warp = tid >> 5, lane = tid & 31;
    int gid  = lane >> 2, tg = lane & 3;
    int wq   = warp * 16;

    int bh = blockIdx.y;
    int q0 = blockIdx.x * 128;
    size_t base  = (size_t)(bh >> 4) * SEQ * DM + (bh & 15) * DH;
    size_t vbase = (size_t)(bh * DH) * SEQ;

    // ---- stage Q (tf32) and extract fragments to registers
    for (int f = tid; f < 128 * 16; f += 256) {
        int q = f >> 4, c4 = (f & 15) << 2;
        float4 v = *(const float4*)(Q + base + (size_t)(q0 + q) * DM + c4);
        float* d = &sQ[q * 70 + c4];
        *(float2*)(d)     = make_float2(to_tf32(v.x), to_tf32(v.y));
        *(float2*)(d + 2) = make_float2(to_tf32(v.z), to_tf32(v.w));
    }
    __syncthreads();

    uint32_t qf[8][4];
    #pragma unroll
    for (int dc = 0; dc < 8; dc++) {
        int r0 = (wq + gid) * 70, r1 = (wq + gid + 8) * 70;
        qf[dc][0] = __float_as_uint(sQ[r0 + dc * 8 + tg]);
        qf[dc][1] = __float_as_uint(sQ[r1 + dc * 8 + tg]);
        qf[dc][2] = __float_as_uint(sQ[r0 + dc * 8 + tg + 4]);
        qf[dc][3] = __float_as_uint(sQ[r1 + dc * 8 + tg + 4]);
    }
    __syncthreads();

    float o[8][4];
    #pragma unroll
    for (int dn = 0; dn < 8; dn++)
        #pragma unroll
        for (int r = 0; r < 4; r++) o[dn][r] = 0.f;
    float m_lo = -INFINITY, m_hi = -INFINITY, l_lo = 0.f, l_hi = 0.f;

    const float scale = 0.125f;   // 1/sqrt(64)

    for (int kt = 0; kt < SEQ / 64; kt++) {
        int k0 = kt * 64;
        // load K tile (natural layout) and VT tile
        for (int f = tid; f < 64 * 16; f += 256) {
            int key = f >> 4, c4 = (f & 15) << 2;
            float4 kv = *(const float4*)(Kb + base + (size_t)(k0 + key) * DM + c4);
            kv.x = to_tf32(kv.x); kv.y = to_tf32(kv.y);
            kv.z = to_tf32(kv.z); kv.w = to_tf32(kv.w);
            *(float4*)&sK[key * KSTR + c4] = kv;

            int d = key, s4 = c4;   // same index decomposition
            float4 vv = *(const float4*)(VT + vbase + (size_t)d * SEQ + k0 + s4);
            vv.x = to_tf32(vv.x); vv.y = to_tf32(vv.y);
            vv.z = to_tf32(vv.z); vv.w = to_tf32(vv.w);
            *(float4*)&sVT[d * VSTR + s4] = vv;
        }
        __syncthreads();

        // ---- S = Q @ K^T
        float s[8][4];
        #pragma unroll
        for (int nt = 0; nt < 8; nt++)
            #pragma unroll
            for (int r = 0; r < 4; r++) s[nt][r] = 0.f;

        #pragma unroll
        for (int dc = 0; dc < 8; dc++) {
            uint32_t b0[8], b1[8];
            #pragma unroll
            for (int nt = 0; nt < 8; nt++) {
                int cc = (nt * 8 + gid) * KSTR;
                b0[nt] = __float_as_uint(sK[cc + dc * 8 + tg]);
                b1[nt] = __float_as_uint(sK[cc + dc * 8 + tg + 4]);
            }
            #pragma unroll
            for (int nt = 0; nt < 8; nt++)
                mma_tf32(s[nt], qf[dc][0], qf[dc][1], qf[dc][2], qf[dc][3],
                         b0[nt], b1[nt]);
        }

        // ---- online softmax (rows lo=gid, hi=gid+8; cols spread over tg-quad)
        float mx_lo = -INFINITY, mx_hi = -INFINITY;
        #pragma unroll
        for (int nt = 0; nt < 8; nt++) {
            s[nt][0] *= scale; s[nt][1] *= scale;
            s[nt][2] *= scale; s[nt][3] *= scale;
            mx_lo = fmaxf(mx_lo, fmaxf(s[nt][0], s[nt][1]));
            mx_hi = fmaxf(mx_hi, fmaxf(s[nt][2], s[nt][3]));
        }
        #pragma unroll
        for (int off = 1; off < 4; off <<= 1) {
            mx_lo = fmaxf(mx_lo, __shfl_xor_sync(0xffffffffu, mx_lo, off));
            mx_hi = fmaxf(mx_hi, __shfl_xor_sync(0xffffffffu, mx_hi, off));
        }
        float mn_lo = fmaxf(m_lo, mx_lo);
        float mn_hi = fmaxf(m_hi, mx_hi);
        float al_lo = __expf(m_lo - mn_lo);
        float al_hi = __expf(m_hi - mn_hi);
        float ps_lo = 0.f, ps_hi = 0.f;
        #pragma unroll
        for (int nt = 0; nt < 8; nt++) {
            s[nt][0] = __expf(s[nt][0] - mn_lo);
            s[nt][1] = __expf(s[nt][1] - mn_lo);
            s[nt][2] = __expf(s[nt][2] - mn_hi);
            s[nt][3] = __expf(s[nt][3] - mn_hi);
            ps_lo += s[nt][0] + s[nt][1];
            ps_hi += s[nt][2] + s[nt][3];
        }
        #pragma unroll
        for (int off = 1; off < 4; off <<= 1) {
            ps_lo += __shfl_xor_sync(0xffffffffu, ps_lo, off);
            ps_hi += __shfl_xor_sync(0xffffffffu, ps_hi, off);
        }
        l_lo = l_lo * al_lo + ps_lo;
        l_hi = l_hi * al_hi + ps_hi;
        m_lo = mn_lo; m_hi = mn_hi;
        #pragma unroll
        for (int dn = 0; dn < 8; dn++) {
            o[dn][0] *= al_lo; o[dn][1] *= al_lo;
            o[dn][2] *= al_hi; o[dn][3] *= al_hi;
        }

        // ---- O += P @ V : P C-frags -> A-frags via shuffles, V^T from smem
        int src0 = gid * 4 + (tg >> 1);
        int src1 = src0 + 2;
        bool odd = (tg & 1);
        #pragma unroll
        for (int ks = 0; ks < 8; ks++) {
            float p0 = to_tf32(s[ks][0]);
            float p1 = to_tf32(s[ks][1]);
            float p2 = to_tf32(s[ks][2]);
            float p3 = to_tf32(s[ks][3]);
            float v00 = __shfl_sync(0xffffffffu, p0, src0);
            float v01 = __shfl_sync(0xffffffffu, p1, src0);
            float v02 = __shfl_sync(0xffffffffu, p2, src0);
            float v03 = __shfl_sync(0xffffffffu, p3, src0);
            float v10 = __shfl_sync(0xffffffffu, p0, src1);
            float v11 = __shfl_sync(0xffffffffu, p1, src1);
            float v12 = __shfl_sync(0xffffffffu, p2, src1);
            float v13 = __shfl_sync(0xffffffffu, p3, src1);
            uint32_t a0 = __float_as_uint(odd ? v01 : v00);
            uint32_t a1 = __float_as_uint(odd ? v03 : v02);
            uint32_t a2 = __float_as_uint(odd ? v11 : v10);
            uint32_t a3 = __float_as_uint(odd ? v13 : v12);

            #pragma unroll
            for (int dn = 0; dn < 8; dn++) {
                int cc = (dn * 8 + gid) * VSTR;
                uint32_t b0 = __float_as_uint(sVT[cc + ks * 8 + tg]);
                uint32_t b1 = __float_as_uint(sVT[cc + ks * 8 + tg + 4]);
                mma_tf32(o[dn], a0, a1, a2, a3, b0, b1);
            }
        }
        __syncthreads();
    }

    // ---- epilogue: normalize and store
    float inv_lo = 1.0f / l_lo;
    float inv_hi = 1.0f / l_hi;
    #pragma unroll
    for (int dn = 0; dn < 8; dn++) {
        int d = dn * 8 + 2 * tg;
        size_t r0 = base + (size_t)(q0 + wq + gid) * DM + d;
        size_t r1 = base + (size_t)(q0 + wq + gid + 8) * DM + d;
        *(float2*)(O + r0) = make_float2(o[dn][0] * inv_lo, o[dn][1] * inv_lo);
        *(float2*)(O + r1) = make_float2(o[dn][2] * inv_hi, o[dn][3] * inv_hi);
    }
}

// ---------------- launcher -------------------------------------------------
#define GEMM256_SMEM ((6144 + 2 * 4224) * (int)sizeof(float))   // 58368 B

extern "C" void kernel_launch(void* const* d_in, const int* in_sizes, int n_in,
                              void* d_out, int out_size)
{
    const float* x      = (const float*)d_in[0];
    const float* Wq     = (const float*)d_in[1];
    const float* bq     = (const float*)d_in[2];
    const float* Wk     = (const float*)d_in[3];
    const float* bk     = (const float*)d_in[4];
    const float* Wv     = (const float*)d_in[5];
    const float* bv     = (const float*)d_in[6];
    const float* Wo     = (const float*)d_in[7];
    const float* bo     = (const float*)d_in[8];
    const float* alpha1 = (const float*)d_in[9];
    const float* beta1  = (const float*)d_in[10];
    const float* alpha2 = (const float*)d_in[11];
    const float* beta2  = (const float*)d_in[12];
    const float* W1     = (const float*)d_in[13];
    const float* b1     = (const float*)d_in[14];
    const float* W2     = (const float*)d_in[15];
    const float* b2     = (const float*)d_in[16];
    float* out = (float*)d_out;

    float *xn, *q, *k, *v, *vt, *ao, *x2, *hn, *h1;
    cudaGetSymbolAddress((void**)&xn, g_xn);
    cudaGetSymbolAddress((void**)&q,  g_q);
    cudaGetSymbolAddress((void**)&k,  g_k);
    cudaGetSymbolAddress((void**)&v,  g_v);
    cudaGetSymbolAddress((void**)&vt, g_vt);
    cudaGetSymbolAddress((void**)&ao, g_ao);
    cudaGetSymbolAddress((void**)&x2, g_x2);
    cudaGetSymbolAddress((void**)&hn, g_hn);
    cudaGetSymbolAddress((void**)&h1, g_h1);

    cudaFuncSetAttribute(qkv_gemm, cudaFuncAttributeMaxDynamicSharedMemorySize, GEMM256_SMEM);
    cudaFuncSetAttribute(tgemm256<false, true>, cudaFuncAttributeMaxDynamicSharedMemorySize, GEMM256_SMEM);

    // 1. x_n = norm1(x)
    norm_kernel<<<ROWS, 256>>>(x, alpha1, beta1, xn);

    // 2. fused Q/K/V projections (384 blocks)
    qkv_gemm<<<dim3(12, ROWS / 128), 256, GEMM256_SMEM>>>(
        xn, Wq, Wk, Wv, bq, bk, bv, q, k, v);

    // 3. V per-head transpose
    vtrans_kernel<<<dim3(SEQ / 64, BATCH * NH), 256>>>(v, vt);

    // 4. attention
    attn2_kernel<<<dim3(SEQ / 128, BATCH * NH), 256>>>(q, k, vt, ao);

    // 5. x2 = x_n + ao@Wo + bo
    tgemm256<false, true><<<dim3(DM / 256, ROWS / 128), 256, GEMM256_SMEM>>>(
        ao, Wo, bo, xn, x2, DM, DM);

    // 6. h_n = norm2(x2)
    norm_kernel<<<ROWS, 256>>>(x2, alpha2, beta2, hn);

    // 7. h1 = relu(h_n@W1 + b1)  (128x128 kernel -> 128 blocks)
    tgemm<true, false><<<dim3(DFF / 128, ROWS / 128), 256>>>(
        hn, W1, b1, nullptr, h1, ROWS, DFF, DM);

    // 8. out = x2 + h1@W2 + b2
    tgemm256<false, true><<<dim3(DM / 256, ROWS / 128), 256, GEMM256_SMEM>>>(
        h1, W2, b2, x2, out, DM, DFF);
}

// round 8
// speedup vs baseline: 1.3869x; 1.3869x over previous
#include <cuda_runtime.h>
#include <cuda_bf16.h>
#include <math.h>
#include <stdint.h>

// Problem constants
#define BATCH 2
#define SEQ   2048
#define DM    1024
#define NH    16
#define DH    64
#define DFF   512
#define ROWS  (BATCH*SEQ)          // 4096

// ---------------- scratch (device globals; no runtime allocation) ----------
__device__ float g_xn[ROWS*DM];    // norm1(x)
__device__ float g_q [ROWS*DM];
__device__ float g_k [ROWS*DM];
__device__ float g_v [ROWS*DM];
__device__ float g_kt[ROWS*DM];    // K transposed per head: [b*16+h][d][s]
__device__ float g_ao[ROWS*DM];    // attention output (pre-Wo)
__device__ float g_x2[ROWS*DM];    // x_n + attn@Wo + bo
__device__ float g_hn[ROWS*DM];    // norm2(x2)
__device__ float g_h1[ROWS*DFF];   // relu(hn@W1+b1)

// ---------------- helpers ---------------------------------------------------
__device__ __forceinline__ float to_tf32(float x) {
    float r;
    asm("cvt.rna.tf32.f32 %0, %1;" : "=f"(r) : "f"(x));
    return r;
}

__device__ __forceinline__ void mma_tf32(float c[4],
                                         uint32_t a0, uint32_t a1, uint32_t a2, uint32_t a3,
                                         uint32_t b0, uint32_t b1) {
    asm volatile(
        "mma.sync.aligned.m16n8k8.row.col.f32.tf32.tf32.f32 "
        "{%0,%1,%2,%3}, {%4,%5,%6,%7}, {%8,%9}, {%0,%1,%2,%3};"
        : "+f"(c[0]), "+f"(c[1]), "+f"(c[2]), "+f"(c[3])
        : "r"(a0), "r"(a1), "r"(a2), "r"(a3), "r"(b0), "r"(b1));
}

// ---------------- NormLayer -------------------------------------------------
__global__ __launch_bounds__(256)
void norm_kernel(const float* __restrict__ X,
                 const float* __restrict__ alpha,
                 const float* __restrict__ beta,
                 float* __restrict__ Y)
{
    int row = blockIdx.x;
    int tid = threadIdx.x;
    const float* xr = X + (size_t)row * DM;

    float4 v = *(const float4*)(xr + tid * 4);
    float s  = v.x + v.y + v.z + v.w;
    float sq = v.x*v.x + v.y*v.y + v.z*v.z + v.w*v.w;

    #pragma unroll
    for (int m = 16; m; m >>= 1) {
        s  += __shfl_xor_sync(0xffffffffu, s,  m);
        sq += __shfl_xor_sync(0xffffffffu, sq, m);
    }
    __shared__ float red[16];
    __shared__ float s_mean, s_rstd;
    int wid  = tid >> 5;
    int lane = tid & 31;
    if (lane == 0) { red[wid] = s; red[8 + wid] = sq; }
    __syncthreads();
    if (tid == 0) {
        float S = 0.f, SQ = 0.f;
        #pragma unroll
        for (int w = 0; w < 8; w++) { S += red[w]; SQ += red[8 + w]; }
        float mean = S * (1.0f / DM);
        float var  = (SQ - (float)DM * mean * mean) * (1.0f / (DM - 1));
        s_mean = mean;
        s_rstd = rsqrtf(var + 1e-6f);
    }
    __syncthreads();
    float mean = s_mean, rstd = s_rstd;

    float4 a = *(const float4*)(alpha + tid * 4);
    float4 b = *(const float4*)(beta  + tid * 4);
    float4 o;
    o.x = a.x * (v.x - mean) * rstd + b.x;
    o.y = a.y * (v.y - mean) * rstd + b.y;
    o.z = a.z * (v.z - mean) * rstd + b.z;
    o.w = a.w * (v.w - mean) * rstd + b.w;
    *(float4*)(Y + (size_t)row * DM + tid * 4) = o;
}

// ---------------- per-head transpose: X[row][h*64+d] -> XT[bh][d][s] --------
__global__ __launch_bounds__(256)
void htrans_kernel(const float* __restrict__ X, float* __restrict__ XT)
{
    __shared__ float ts[64 * 65];
    int tid = threadIdx.x;
    int bh = blockIdx.y;
    int s0 = blockIdx.x * 64;
    size_t base = (size_t)(bh >> 4) * SEQ * DM + (bh & 15) * DH;

    for (int f = tid; f < 64 * 16; f += 256) {
        int s = f >> 4, c4 = (f & 15) << 2;
        float4 v = *(const float4*)(X + base + (size_t)(s0 + s) * DM + c4);
        ts[s * 65 + c4 + 0] = v.x;
        ts[s * 65 + c4 + 1] = v.y;
        ts[s * 65 + c4 + 2] = v.z;
        ts[s * 65 + c4 + 3] = v.w;
    }
    __syncthreads();
    for (int f = tid; f < 64 * 16; f += 256) {
        int d = f >> 4, s4 = (f & 15) << 2;
        float4 w;
        w.x = ts[(s4 + 0) * 65 + d];
        w.y = ts[(s4 + 1) * 65 + d];
        w.z = ts[(s4 + 2) * 65 + d];
        w.w = ts[(s4 + 3) * 65 + d];
        *(float4*)(XT + (size_t)(bh * DH + d) * SEQ + s0 + s4) = w;
    }
}

// ---------------- tf32 tensor-core GEMM body (128x128 tile) ----------------
#define SA_STR 20
#define SB_STR 136
template<bool RELU, bool HAS_RES>
__device__ __forceinline__ void gemm_body(
    const float* __restrict__ A, const float* __restrict__ B,
    const float* __restrict__ bias, const float* __restrict__ Res,
    float* __restrict__ C, int N, int K, int bm, int bn,
    float* sAraw, float* sBraw)
{
    float* sA[2] = { sAraw, sAraw + 128 * SA_STR };
    float* sB[2] = { sBraw, sBraw + 16 * SB_STR };

    int tid  = threadIdx.x;
    int warp = tid >> 5, lane = tid & 31;
    int gid  = lane >> 2, tg = lane & 3;
    int wm   = (warp & 1) * 64;
    int wn   = (warp >> 1) * 32;

    int am[2], ac4[2], bk[2], bn4[2];
    #pragma unroll
    for (int i = 0; i < 2; i++) {
        int f = tid + 256 * i;
        am[i]  = f >> 2;
        ac4[i] = (f & 3) << 2;
        bk[i]  = f >> 5;
        bn4[i] = (f & 31) << 2;
    }
    const float* Abase = A + (size_t)(bm * 128) * K;
    const float* Bbase = B + bn * 128;

    int nk = K >> 4;

    #pragma unroll
    for (int i = 0; i < 2; i++) {
        float4 va = *(const float4*)(Abase + (size_t)am[i] * K + ac4[i]);
        va.x = to_tf32(va.x); va.y = to_tf32(va.y);
        va.z = to_tf32(va.z); va.w = to_tf32(va.w);
        *(float4*)&sA[0][am[i] * SA_STR + ac4[i]] = va;
        float4 vb = *(const float4*)(Bbase + (size_t)bk[i] * N + bn4[i]);
        vb.x = to_tf32(vb.x); vb.y = to_tf32(vb.y);
        vb.z = to_tf32(vb.z); vb.w = to_tf32(vb.w);
        *(float4*)&sB[0][bk[i] * SB_STR + bn4[i]] = vb;
    }
    __syncthreads();

    float acc[4][4][4];
    #pragma unroll
    for (int mt = 0; mt < 4; mt++)
        #pragma unroll
        for (int nt = 0; nt < 4; nt++)
            #pragma unroll
            for (int r = 0; r < 4; r++) acc[mt][nt][r] = 0.f;

    int cur = 0;
    for (int kt = 0; kt < nk; kt++) {
        float4 va[2], vb[2];
        bool has_next = (kt + 1 < nk);
        if (has_next) {
            int k0 = (kt + 1) << 4;
            #pragma unroll
            for (int i = 0; i < 2; i++) {
                va[i] = *(const float4*)(Abase + (size_t)am[i] * K + k0 + ac4[i]);
                vb[i] = *(const float4*)(Bbase + (size_t)(k0 + bk[i]) * N + bn4[i]);
            }
        }

        const float* As = sA[cur];
        const float* Bs = sB[cur];
        #pragma unroll
        for (int kk = 0; kk < 16; kk += 8) {
            uint32_t af[4][4], bf[4][2];
            #pragma unroll
            for (int mt = 0; mt < 4; mt++) {
                int r0 = (wm + mt * 16 + gid) * SA_STR;
                int r1 = (wm + mt * 16 + gid + 8) * SA_STR;
                af[mt][0] = __float_as_uint(As[r0 + kk + tg]);
                af[mt][1] = __float_as_uint(As[r1 + kk + tg]);
                af[mt][2] = __float_as_uint(As[r0 + kk + tg + 4]);
                af[mt][3] = __float_as_uint(As[r1 + kk + tg + 4]);
            }
            #pragma unroll
            for (int nt = 0; nt < 4; nt++) {
                int cc = wn + nt * 8 + gid;
                bf[nt][0] = __float_as_uint(Bs[(kk + tg) * SB_STR + cc]);
                bf[nt][1] = __float_as_uint(Bs[(kk + tg + 4) * SB_STR + cc]);
            }
            #pragma unroll
            for (int mt = 0; mt < 4; mt++)
                #pragma unroll
                for (int nt = 0; nt < 4; nt++)
                    mma_tf32(acc[mt][nt], af[mt][0], af[mt][1], af[mt][2], af[mt][3],
                             bf[nt][0], bf[nt][1]);
        }

        if (has_next) {
            int nxt = cur ^ 1;
            #pragma unroll
            for (int i = 0; i < 2; i++) {
                va[i].x = to_tf32(va[i].x); va[i].y = to_tf32(va[i].y);
                va[i].z = to_tf32(va[i].z); va[i].w = to_tf32(va[i].w);
                *(float4*)&sA[nxt][am[i] * SA_STR + ac4[i]] = va[i];
                vb[i].x = to_tf32(vb[i].x); vb[i].y = to_tf32(vb[i].y);
                vb[i].z = to_tf32(vb[i].z); vb[i].w = to_tf32(vb[i].w);
                *(float4*)&sB[nxt][bk[i] * SB_STR + bn4[i]] = vb[i];
            }
            __syncthreads();
            cur = nxt;
        }
    }

    #pragma unroll
    for (int nt = 0; nt < 4; nt++) {
        int col = bn * 128 + wn + nt * 8 + 2 * tg;
        float2 bv = *(const float2*)(bias + col);
        #pragma unroll
        for (int mt = 0; mt < 4; mt++) {
            int r0 = bm * 128 + wm + mt * 16 + gid;
            int r1 = r0 + 8;
            float2 c0 = make_float2(acc[mt][nt][0] + bv.x, acc[mt][nt][1] + bv.y);
            float2 c1 = make_float2(acc[mt][nt][2] + bv.x, acc[mt][nt][3] + bv.y);
            if (RELU) {
                c0.x = fmaxf(c0.x, 0.f); c0.y = fmaxf(c0.y, 0.f);
                c1.x = fmaxf(c1.x, 0.f); c1.y = fmaxf(c1.y, 0.f);
            }
            if (HAS_RES) {
                float2 r0v = *(const float2*)(Res + (size_t)r0 * N + col);
                float2 r1v = *(const float2*)(Res + (size_t)r1 * N + col);
                c0.x += r0v.x; c0.y += r0v.y;
                c1.x += r1v.x; c1.y += r1v.y;
            }
            *(float2*)(C + (size_t)r0 * N + col) = c0;
            *(float2*)(C + (size_t)r1 * N + col) = c1;
        }
    }
}

template<bool RELU, bool HAS_RES>
__global__ __launch_bounds__(256)
void tgemm(const float* __restrict__ A, const float* __restrict__ B,
           const float* __restrict__ bias, const float* __restrict__ Res,
           float* __restrict__ C, int N, int K)
{
    __shared__ float sA[2 * 128 * SA_STR];
    __shared__ float sB[2 * 16 * SB_STR];
    gemm_body<RELU, HAS_RES>(A, B, bias, Res, C, N, K,
                             blockIdx.y, blockIdx.x, sA, sB);
}

// fused QKV: blockIdx.x in 0..23 -> (weight select = x>>3, col block = x&7)
__global__ __launch_bounds__(256)
void qkv_gemm(const float* __restrict__ A,
              const float* __restrict__ Wq, const float* __restrict__ Wk,
              const float* __restrict__ Wv,
              const float* __restrict__ bq, const float* __restrict__ bk,
              const float* __restrict__ bv,
              float* __restrict__ Oq, float* __restrict__ Ok, float* __restrict__ Ov)
{
    __shared__ float sA[2 * 128 * SA_STR];
    __shared__ float sB[2 * 16 * SB_STR];
    int sel = blockIdx.x >> 3;
    int bn  = blockIdx.x & 7;
    const float* B    = (sel == 0) ? Wq : (sel == 1) ? Wk : Wv;
    const float* bias = (sel == 0) ? bq : (sel == 1) ? bk : bv;
    float* C          = (sel == 0) ? Oq : (sel == 1) ? Ok : Ov;
    gemm_body<false, false>(A, B, bias, nullptr, C, DM, DM,
                            blockIdx.y, bn, sA, sB);
}

// ---------------- tf32 mma flash attention (R6 layout, pre-transposed K) ---
// 128 threads (4 warps), 64 queries/block, 64-key tiles.
// sKT: [d][key] stride 72, loaded coalesced from g_kt (no in-kernel transpose)
// sV:  [key][d] stride 72 (natural layout; PV B-frag reads conflict-free)
// sP:  [q][key] stride 72, per-warp rows only -> syncwarp suffices.
#define AT_STR 72
__global__ __launch_bounds__(128)
void attn_mma_kernel(const float* __restrict__ Q, const float* __restrict__ KT,
                     const float* __restrict__ Vb, float* __restrict__ O)
{
    extern __shared__ float sm[];
    float* sKT = sm;                    // [d=64][key=64+pad]
    float* sV  = sm + 64 * AT_STR;      // [key=64][d=64+pad]
    float* sP  = sm + 2 * 64 * AT_STR;  // Q staging, then P [q][key]

    int tid  = threadIdx.x;
    int warp = tid >> 5, lane = tid & 31;
    int gid  = lane >> 2, tg = lane & 3;
    int wq   = warp * 16;

    int bh = blockIdx.y;
    int q0 = blockIdx.x * 64;
    size_t base   = (size_t)(bh >> 4) * SEQ * DM + (bh & 15) * DH;
    size_t ktbase = (size_t)(bh * DH) * SEQ;

    // ---- stage Q tile (tf32) into sP, extract fragments to registers
    for (int f = tid; f < 64 * 16; f += 128) {
        int q = f >> 4, c4 = (f & 15) << 2;
        float4 v = *(const float4*)(Q + base + (size_t)(q0 + q) * DM + c4);
        v.x = to_tf32(v.x); v.y = to_tf32(v.y);
        v.z = to_tf32(v.z); v.w = to_tf32(v.w);
        *(float4*)&sP[q * AT_STR + c4] = v;
    }
    __syncthreads();

    uint32_t qf[8][4];
    #pragma unroll
    for (int ks = 0; ks < 8; ks++) {
        int k = ks * 8;
        int r0 = (wq + gid) * AT_STR, r1 = (wq + gid + 8) * AT_STR;
        qf[ks][0] = __float_as_uint(sP[r0 + k + tg]);
        qf[ks][1] = __float_as_uint(sP[r1 + k + tg]);
        qf[ks][2] = __float_as_uint(sP[r0 + k + tg + 4]);
        qf[ks][3] = __float_as_uint(sP[r1 + k + tg + 4]);
    }
    __syncthreads();

    float o[8][4];
    #pragma unroll
    for (int nt = 0; nt < 8; nt++)
        #pragma unroll
        for (int r = 0; r < 4; r++) o[nt][r] = 0.f;
    float m_lo = -INFINITY, m_hi = -INFINITY, l_lo = 0.f, l_hi = 0.f;

    const float scale = 0.125f;   // 1/sqrt(64)

    for (int kt = 0; kt < SEQ / 64; kt++) {
        int k0 = kt * 64;
        // ---- load K^T tile (coalesced, already per-head transposed) and V tile
        for (int f = tid; f < 64 * 16; f += 128) {
            int r = f >> 4, c4 = (f & 15) << 2;
            // K^T: row r = d, cols = keys
            float4 kv = *(const float4*)(KT + ktbase + (size_t)r * SEQ + k0 + c4);
            kv.x = to_tf32(kv.x); kv.y = to_tf32(kv.y);
            kv.z = to_tf32(kv.z); kv.w = to_tf32(kv.w);
            *(float4*)&sKT[r * AT_STR + c4] = kv;
            // V natural: row r = key, cols = d
            float4 vv = *(const float4*)(Vb + base + (size_t)(k0 + r) * DM + c4);
            vv.x = to_tf32(vv.x); vv.y = to_tf32(vv.y);
            vv.z = to_tf32(vv.z); vv.w = to_tf32(vv.w);
            *(float4*)&sV[r * AT_STR + c4] = vv;
        }
        __syncthreads();

        // ---- S = Q @ K^T
        float s[8][4];
        #pragma unroll
        for (int nt = 0; nt < 8; nt++)
            #pragma unroll
            for (int r = 0; r < 4; r++) s[nt][r] = 0.f;

        #pragma unroll
        for (int ks = 0; ks < 8; ks++) {
            uint32_t bf[8][2];
            int kr0 = (ks * 8 + tg) * AT_STR;
            int kr1 = (ks * 8 + tg + 4) * AT_STR;
            #pragma unroll
            for (int nt = 0; nt < 8; nt++) {
                int cc = nt * 8 + gid;
                bf[nt][0] = __float_as_uint(sKT[kr0 + cc]);
                bf[nt][1] = __float_as_uint(sKT[kr1 + cc]);
            }
            #pragma unroll
            for (int nt = 0; nt < 8; nt++)
                mma_tf32(s[nt], qf[ks][0], qf[ks][1], qf[ks][2], qf[ks][3],
                         bf[nt][0], bf[nt][1]);
        }

        // ---- online softmax (rows: q_lo = wq+gid, q_hi = wq+gid+8)
        float mx_lo = -INFINITY, mx_hi = -INFINITY;
        #pragma unroll
        for (int nt = 0; nt < 8; nt++) {
            s[nt][0] *= scale; s[nt][1] *= scale;
            s[nt][2] *= scale; s[nt][3] *= scale;
            mx_lo = fmaxf(mx_lo, fmaxf(s[nt][0], s[nt][1]));
            mx_hi = fmaxf(mx_hi, fmaxf(s[nt][2], s[nt][3]));
        }
        #pragma unroll
        for (int off = 1; off < 4; off <<= 1) {
            mx_lo = fmaxf(mx_lo, __shfl_xor_sync(0xffffffffu, mx_lo, off));
            mx_hi = fmaxf(mx_hi, __shfl_xor_sync(0xffffffffu, mx_hi, off));
        }
        float mn_lo = fmaxf(m_lo, mx_lo);
        float mn_hi = fmaxf(m_hi, mx_hi);
        float al_lo = __expf(m_lo - mn_lo);
        float al_hi = __expf(m_hi - mn_hi);
        float ps_lo = 0.f, ps_hi = 0.f;
        #pragma unroll
        for (int nt = 0; nt < 8; nt++) {
            s[nt][0] = __expf(s[nt][0] - mn_lo);
            s[nt][1] = __expf(s[nt][1] - mn_lo);
            s[nt][2] = __expf(s[nt][2] - mn_hi);
            s[nt][3] = __expf(s[nt][3] - mn_hi);
            ps_lo += s[nt][0] + s[nt][1];
            ps_hi += s[nt][2] + s[nt][3];
        }
        #pragma unroll
        for (int off = 1; off < 4; off <<= 1) {
            ps_lo += __shfl_xor_sync(0xffffffffu, ps_lo, off);
            ps_hi += __shfl_xor_sync(0xffffffffu, ps_hi, off);
        }
        l_lo = l_lo * al_lo + ps_lo;
        l_hi = l_hi * al_hi + ps_hi;
        m_lo = mn_lo; m_hi = mn_hi;
        #pragma unroll
        for (int nt = 0; nt < 8; nt++) {
            o[nt][0] *= al_lo; o[nt][1] *= al_lo;
            o[nt][2] *= al_hi; o[nt][3] *= al_hi;
        }

        // ---- write P (tf32) to sP; only own warp's rows -> warp sync only
        #pragma unroll
        for (int nt = 0; nt < 8; nt++) {
            int kc = nt * 8 + 2 * tg;
            float2 p0 = make_float2(to_tf32(s[nt][0]), to_tf32(s[nt][1]));
            float2 p1 = make_float2(to_tf32(s[nt][2]), to_tf32(s[nt][3]));
            *(float2*)&sP[(wq + gid) * AT_STR + kc]     = p0;
            *(float2*)&sP[(wq + gid + 8) * AT_STR + kc] = p1;
        }
        __syncwarp();

        // ---- O += P @ V
        #pragma unroll
        for (int ks = 0; ks < 8; ks++) {
            uint32_t pa[4], bf[8][2];
            int r0 = (wq + gid) * AT_STR, r1 = (wq + gid + 8) * AT_STR;
            pa[0] = __float_as_uint(sP[r0 + ks * 8 + tg]);
            pa[1] = __float_as_uint(sP[r1 + ks * 8 + tg]);
            pa[2] = __float_as_uint(sP[r0 + ks * 8 + tg + 4]);
            pa[3] = __float_as_uint(sP[r1 + ks * 8 + tg + 4]);
            int vr0 = (ks * 8 + tg) * AT_STR;
            int vr1 = (ks * 8 + tg + 4) * AT_STR;
            #pragma unroll
            for (int nt = 0; nt < 8; nt++) {
                int cc = nt * 8 + gid;
                bf[nt][0] = __float_as_uint(sV[vr0 + cc]);
                bf[nt][1] = __float_as_uint(sV[vr1 + cc]);
            }
            #pragma unroll
            for (int nt = 0; nt < 8; nt++)
                mma_tf32(o[nt], pa[0], pa[1], pa[2], pa[3], bf[nt][0], bf[nt][1]);
        }
        __syncthreads();   // protect sKT/sV before next iteration's loads
    }

    // ---- epilogue: normalize and store
    float inv_lo = 1.0f / l_lo;
    float inv_hi = 1.0f / l_hi;
    #pragma unroll
    for (int nt = 0; nt < 8; nt++) {
        int d = nt * 8 + 2 * tg;
        size_t r0 = base + (size_t)(q0 + wq + gid) * DM + d;
        size_t r1 = base + (size_t)(q0 + wq + gid + 8) * DM + d;
        *(float2*)(O + r0) = make_float2(o[nt][0] * inv_lo, o[nt][1] * inv_lo);
        *(float2*)(O + r1) = make_float2(o[nt][2] * inv_hi, o[nt][3] * inv_hi);
    }
}

// ---------------- launcher -------------------------------------------------
extern "C" void kernel_launch(void* const* d_in, const int* in_sizes, int n_in,
                              void* d_out, int out_size)
{
    const float* x      = (const float*)d_in[0];
    const float* Wq     = (const float*)d_in[1];
    const float* bq     = (const float*)d_in[2];
    const float* Wk     = (const float*)d_in[3];
    const float* bk     = (const float*)d_in[4];
    const float* Wv     = (const float*)d_in[5];
    const float* bv     = (const float*)d_in[6];
    const float* Wo     = (const float*)d_in[7];
    const float* bo     = (const float*)d_in[8];
    const float* alpha1 = (const float*)d_in[9];
    const float* beta1  = (const float*)d_in[10];
    const float* alpha2 = (const float*)d_in[11];
    const float* beta2  = (const float*)d_in[12];
    const float* W1     = (const float*)d_in[13];
    const float* b1     = (const float*)d_in[14];
    const float* W2     = (const float*)d_in[15];
    const float* b2     = (const float*)d_in[16];
    float* out = (float*)d_out;

    float *xn, *q, *k, *v, *kt, *ao, *x2, *hn, *h1;
    cudaGetSymbolAddress((void**)&xn, g_xn);
    cudaGetSymbolAddress((void**)&q,  g_q);
    cudaGetSymbolAddress((void**)&k,  g_k);
    cudaGetSymbolAddress((void**)&v,  g_v);
    cudaGetSymbolAddress((void**)&kt, g_kt);
    cudaGetSymbolAddress((void**)&ao, g_ao);
    cudaGetSymbolAddress((void**)&x2, g_x2);
    cudaGetSymbolAddress((void**)&hn, g_hn);
    cudaGetSymbolAddress((void**)&h1, g_h1);

    // 1. x_n = norm1(x)
    norm_kernel<<<ROWS, 256>>>(x, alpha1, beta1, xn);

    // 2. fused Q/K/V projections (768 blocks)
    qkv_gemm<<<dim3(24, ROWS / 128), 256>>>(xn, Wq, Wk, Wv, bq, bk, bv, q, k, v);

    // 3. K per-head transpose
    htrans_kernel<<<dim3(SEQ / 64, BATCH * NH), 256>>>(k, kt);

    // 4. attention
    int att_smem = 3 * 64 * AT_STR * (int)sizeof(float);   // 55296 B
    cudaFuncSetAttribute(attn_mma_kernel, cudaFuncAttributeMaxDynamicSharedMemorySize, att_smem);
    attn_mma_kernel<<<dim3(SEQ / 64, BATCH * NH), 128, att_smem>>>(q, kt, v, ao);

    // 5. x2 = x_n + ao@Wo + bo
    tgemm<false, true><<<dim3(DM / 128, ROWS / 128), 256>>>(ao, Wo, bo, xn, x2, DM, DM);

    // 6. h_n = norm2(x2)
    norm_kernel<<<ROWS, 256>>>(x2, alpha2, beta2, hn);

    // 7. h1 = relu(h_n@W1 + b1)
    tgemm<true, false><<<dim3(DFF / 128, ROWS / 128), 256>>>(hn, W1, b1, nullptr, h1, DFF, DM);

    // 8. out = x2 + h1@W2 + b2
    tgemm<false, true><<<dim3(DM / 128, ROWS / 128), 256>>>(h1, W2, b2, x2, out, DM, DFF);
}

// round 10
// speedup vs baseline: 1.4670x; 1.0578x over previous
#include <cuda_runtime.h>
#include <cuda_bf16.h>
#include <math.h>
#include <stdint.h>

// Problem constants
#define BATCH 2
#define SEQ   2048
#define DM    1024
#define NH    16
#define DH    64
#define DFF   512
#define ROWS  (BATCH*SEQ)          // 4096

// ---------------- scratch (device globals; no runtime allocation) ----------
__device__ float g_xn[ROWS*DM];    // norm1(x)
__device__ float g_q [ROWS*DM];    // tf32-rounded Q
__device__ float g_k [ROWS*DM];    // tf32-rounded K
__device__ float g_v [ROWS*DM];    // tf32-rounded V
__device__ float g_kt[ROWS*DM];    // K transposed per head: [b*16+h][d][s]
__device__ float g_ao[ROWS*DM];    // attention output (pre-Wo)
__device__ float g_x2[ROWS*DM];    // x_n + attn@Wo + bo
__device__ float g_hn[ROWS*DM];    // norm2(x2)
__device__ float g_h1[ROWS*DFF];   // relu(hn@W1+b1)

// ---------------- helpers ---------------------------------------------------
__device__ __forceinline__ float to_tf32(float x) {
    float r;
    asm("cvt.rna.tf32.f32 %0, %1;" : "=f"(r) : "f"(x));
    return r;
}

__device__ __forceinline__ void mma_tf32(float c[4],
                                         uint32_t a0, uint32_t a1, uint32_t a2, uint32_t a3,
                                         uint32_t b0, uint32_t b1) {
    asm volatile(
        "mma.sync.aligned.m16n8k8.row.col.f32.tf32.tf32.f32 "
        "{%0,%1,%2,%3}, {%4,%5,%6,%7}, {%8,%9}, {%0,%1,%2,%3};"
        : "+f"(c[0]), "+f"(c[1]), "+f"(c[2]), "+f"(c[3])
        : "r"(a0), "r"(a1), "r"(a2), "r"(a3), "r"(b0), "r"(b1));
}

__device__ __forceinline__ void cp_async16(uint32_t sdst, const void* gsrc) {
    asm volatile("cp.async.cg.shared.global [%0], [%1], 16;"
                 :: "r"(sdst), "l"(gsrc) : "memory");
}
__device__ __forceinline__ void cp_commit() {
    asm volatile("cp.async.commit_group;" ::: "memory");
}
__device__ __forceinline__ void cp_wait1() {
    asm volatile("cp.async.wait_group 1;" ::: "memory");
}
__device__ __forceinline__ void cp_wait0() {
    asm volatile("cp.async.wait_group 0;" ::: "memory");
}

// ---------------- NormLayer -------------------------------------------------
__global__ __launch_bounds__(256)
void norm_kernel(const float* __restrict__ X,
                 const float* __restrict__ alpha,
                 const float* __restrict__ beta,
                 float* __restrict__ Y)
{
    int row = blockIdx.x;
    int tid = threadIdx.x;
    const float* xr = X + (size_t)row * DM;

    float4 v = *(const float4*)(xr + tid * 4);
    float s  = v.x + v.y + v.z + v.w;
    float sq = v.x*v.x + v.y*v.y + v.z*v.z + v.w*v.w;

    #pragma unroll
    for (int m = 16; m; m >>= 1) {
        s  += __shfl_xor_sync(0xffffffffu, s,  m);
        sq += __shfl_xor_sync(0xffffffffu, sq, m);
    }
    __shared__ float red[16];
    __shared__ float s_mean, s_rstd;
    int wid  = tid >> 5;
    int lane = tid & 31;
    if (lane == 0) { red[wid] = s; red[8 + wid] = sq; }
    __syncthreads();
    if (tid == 0) {
        float S = 0.f, SQ = 0.f;
        #pragma unroll
        for (int w = 0; w < 8; w++) { S += red[w]; SQ += red[8 + w]; }
        float mean = S * (1.0f / DM);
        float var  = (SQ - (float)DM * mean * mean) * (1.0f / (DM - 1));
        s_mean = mean;
        s_rstd = rsqrtf(var + 1e-6f);
    }
    __syncthreads();
    float mean = s_mean, rstd = s_rstd;

    float4 a = *(const float4*)(alpha + tid * 4);
    float4 b = *(const float4*)(beta  + tid * 4);
    float4 o;
    o.x = a.x * (v.x - mean) * rstd + b.x;
    o.y = a.y * (v.y - mean) * rstd + b.y;
    o.z = a.z * (v.z - mean) * rstd + b.z;
    o.w = a.w * (v.w - mean) * rstd + b.w;
    *(float4*)(Y + (size_t)row * DM + tid * 4) = o;
}

// ---------------- per-head transpose: X[row][h*64+d] -> XT[bh][d][s] --------
__global__ __launch_bounds__(256)
void htrans_kernel(const float* __restrict__ X, float* __restrict__ XT)
{
    __shared__ float ts[64 * 65];
    int tid = threadIdx.x;
    int bh = blockIdx.y;
    int s0 = blockIdx.x * 64;
    size_t base = (size_t)(bh >> 4) * SEQ * DM + (bh & 15) * DH;

    for (int f = tid; f < 64 * 16; f += 256) {
        int s = f >> 4, c4 = (f & 15) << 2;
        float4 v = *(const float4*)(X + base + (size_t)(s0 + s) * DM + c4);
        ts[s * 65 + c4 + 0] = v.x;
        ts[s * 65 + c4 + 1] = v.y;
        ts[s * 65 + c4 + 2] = v.z;
        ts[s * 65 + c4 + 3] = v.w;
    }
    __syncthreads();
    for (int f = tid; f < 64 * 16; f += 256) {
        int d = f >> 4, s4 = (f & 15) << 2;
        float4 w;
        w.x = ts[(s4 + 0) * 65 + d];
        w.y = ts[(s4 + 1) * 65 + d];
        w.z = ts[(s4 + 2) * 65 + d];
        w.w = ts[(s4 + 3) * 65 + d];
        *(float4*)(XT + (size_t)(bh * DH + d) * SEQ + s0 + s4) = w;
    }
}

// ---------------- tf32 tensor-core GEMM body (128x128 tile) ----------------
// CVT_OUT: round outputs to tf32 (RNA) at store time (for Q/K/V producers).
#define SA_STR 20
#define SB_STR 136
template<bool RELU, bool HAS_RES, bool CVT_OUT>
__device__ __forceinline__ void gemm_body(
    const float* __restrict__ A, const float* __restrict__ B,
    const float* __restrict__ bias, const float* __restrict__ Res,
    float* __restrict__ C, int N, int K, int bm, int bn,
    float* sAraw, float* sBraw)
{
    float* sA[2] = { sAraw, sAraw + 128 * SA_STR };
    float* sB[2] = { sBraw, sBraw + 16 * SB_STR };

    int tid  = threadIdx.x;
    int warp = tid >> 5, lane = tid & 31;
    int gid  = lane >> 2, tg = lane & 3;
    int wm   = (warp & 1) * 64;
    int wn   = (warp >> 1) * 32;

    int am[2], ac4[2], bk[2], bn4[2];
    #pragma unroll
    for (int i = 0; i < 2; i++) {
        int f = tid + 256 * i;
        am[i]  = f >> 2;
        ac4[i] = (f & 3) << 2;
        bk[i]  = f >> 5;
        bn4[i] = (f & 31) << 2;
    }
    const float* Abase = A + (size_t)(bm * 128) * K;
    const float* Bbase = B + bn * 128;

    int nk = K >> 4;

    #pragma unroll
    for (int i = 0; i < 2; i++) {
        float4 va = *(const float4*)(Abase + (size_t)am[i] * K + ac4[i]);
        va.x = to_tf32(va.x); va.y = to_tf32(va.y);
        va.z = to_tf32(va.z); va.w = to_tf32(va.w);
        *(float4*)&sA[0][am[i] * SA_STR + ac4[i]] = va;
        float4 vb = *(const float4*)(Bbase + (size_t)bk[i] * N + bn4[i]);
        vb.x = to_tf32(vb.x); vb.y = to_tf32(vb.y);
        vb.z = to_tf32(vb.z); vb.w = to_tf32(vb.w);
        *(float4*)&sB[0][bk[i] * SB_STR + bn4[i]] = vb;
    }
    __syncthreads();

    float acc[4][4][4];
    #pragma unroll
    for (int mt = 0; mt < 4; mt++)
        #pragma unroll
        for (int nt = 0; nt < 4; nt++)
            #pragma unroll
            for (int r = 0; r < 4; r++) acc[mt][nt][r] = 0.f;

    int cur = 0;
    for (int kt = 0; kt < nk; kt++) {
        float4 va[2], vb[2];
        bool has_next = (kt + 1 < nk);
        if (has_next) {
            int k0 = (kt + 1) << 4;
            #pragma unroll
            for (int i = 0; i < 2; i++) {
                va[i] = *(const float4*)(Abase + (size_t)am[i] * K + k0 + ac4[i]);
                vb[i] = *(const float4*)(Bbase + (size_t)(k0 + bk[i]) * N + bn4[i]);
            }
        }

        const float* As = sA[cur];
        const float* Bs = sB[cur];
        #pragma unroll
        for (int kk = 0; kk < 16; kk += 8) {
            uint32_t af[4][4], bf[4][2];
            #pragma unroll
            for (int mt = 0; mt < 4; mt++) {
                int r0 = (wm + mt * 16 + gid) * SA_STR;
                int r1 = (wm + mt * 16 + gid + 8) * SA_STR;
                af[mt][0] = __float_as_uint(As[r0 + kk + tg]);
                af[mt][1] = __float_as_uint(As[r1 + kk + tg]);
                af[mt][2] = __float_as_uint(As[r0 + kk + tg + 4]);
                af[mt][3] = __float_as_uint(As[r1 + kk + tg + 4]);
            }
            #pragma unroll
            for (int nt = 0; nt < 4; nt++) {
                int cc = wn + nt * 8 + gid;
                bf[nt][0] = __float_as_uint(Bs[(kk + tg) * SB_STR + cc]);
                bf[nt][1] = __float_as_uint(Bs[(kk + tg + 4) * SB_STR + cc]);
            }
            #pragma unroll
            for (int mt = 0; mt < 4; mt++)
                #pragma unroll
                for (int nt = 0; nt < 4; nt++)
                    mma_tf32(acc[mt][nt], af[mt][0], af[mt][1], af[mt][2], af[mt][3],
                             bf[nt][0], bf[nt][1]);
        }

        if (has_next) {
            int nxt = cur ^ 1;
            #pragma unroll
            for (int i = 0; i < 2; i++) {
                va[i].x = to_tf32(va[i].x); va[i].y = to_tf32(va[i].y);
                va[i].z = to_tf32(va[i].z); va[i].w = to_tf32(va[i].w);
                *(float4*)&sA[nxt][am[i] * SA_STR + ac4[i]] = va[i];
                vb[i].x = to_tf32(vb[i].x); vb[i].y = to_tf32(vb[i].y);
                vb[i].z = to_tf32(vb[i].z); vb[i].w = to_tf32(vb[i].w);
                *(float4*)&sB[nxt][bk[i] * SB_STR + bn4[i]] = vb[i];
            }
            __syncthreads();
            cur = nxt;
        }
    }

    #pragma unroll
    for (int nt = 0; nt < 4; nt++) {
        int col = bn * 128 + wn + nt * 8 + 2 * tg;
        float2 bv = *(const float2*)(bias + col);
        #pragma unroll
        for (int mt = 0; mt < 4; mt++) {
            int r0 = bm * 128 + wm + mt * 16 + gid;
            int r1 = r0 + 8;
            float2 c0 = make_float2(acc[mt][nt][0] + bv.x, acc[mt][nt][1] + bv.y);
            float2 c1 = make_float2(acc[mt][nt][2] + bv.x, acc[mt][nt][3] + bv.y);
            if (RELU) {
                c0.x = fmaxf(c0.x, 0.f); c0.y = fmaxf(c0.y, 0.f);
                c1.x = fmaxf(c1.x, 0.f); c1.y = fmaxf(c1.y, 0.f);
            }
            if (HAS_RES) {
                float2 r0v = *(const float2*)(Res + (size_t)r0 * N + col);
                float2 r1v = *(const float2*)(Res + (size_t)r1 * N + col);
                c0.x += r0v.x; c0.y += r0v.y;
                c1.x += r1v.x; c1.y += r1v.y;
            }
            if (CVT_OUT) {
                c0.x = to_tf32(c0.x); c0.y = to_tf32(c0.y);
                c1.x = to_tf32(c1.x); c1.y = to_tf32(c1.y);
            }
            *(float2*)(C + (size_t)r0 * N + col) = c0;
            *(float2*)(C + (size_t)r1 * N + col) = c1;
        }
    }
}

template<bool RELU, bool HAS_RES>
__global__ __launch_bounds__(256)
void tgemm(const float* __restrict__ A, const float* __restrict__ B,
           const float* __restrict__ bias, const float* __restrict__ Res,
           float* __restrict__ C, int N, int K)
{
    __shared__ float sA[2 * 128 * SA_STR];
    __shared__ float sB[2 * 16 * SB_STR];
    gemm_body<RELU, HAS_RES, false>(A, B, bias, Res, C, N, K,
                                    blockIdx.y, blockIdx.x, sA, sB);
}

// fused QKV: blockIdx.x in 0..23 -> (weight select = x>>3, col block = x&7)
// Outputs rounded to tf32 so attention can consume raw bits.
__global__ __launch_bounds__(256)
void qkv_gemm(const float* __restrict__ A,
              const float* __restrict__ Wq, const float* __restrict__ Wk,
              const float* __restrict__ Wv,
              const float* __restrict__ bq, const float* __restrict__ bk,
              const float* __restrict__ bv,
              float* __restrict__ Oq, float* __restrict__ Ok, float* __restrict__ Ov)
{
    __shared__ float sA[2 * 128 * SA_STR];
    __shared__ float sB[2 * 16 * SB_STR];
    int sel = blockIdx.x >> 3;
    int bn  = blockIdx.x & 7;
    const float* B    = (sel == 0) ? Wq : (sel == 1) ? Wk : Wv;
    const float* bias = (sel == 0) ? bq : (sel == 1) ? bk : bv;
    float* C          = (sel == 0) ? Oq : (sel == 1) ? Ok : Ov;
    gemm_body<false, false, true>(A, B, bias, nullptr, C, DM, DM,
                                  blockIdx.y, bn, sA, sB);
}

// ---------------- flash attention: cp.async double-buffered ----------------
// 128 threads (4 warps), 64 queries/block, 64-key tiles, K/V pipelined.
// Inputs are pre-rounded tf32 (from qkv epilogue); loads are raw cp.async.
// sKT[d][key] str 72, sV[key][d] str 72 (both double-buffered);
// sP (Q staging, then P) str 76 -> all frag accesses bank-conflict-free.
#define KSTR 72
#define PSTR 76
#define SM_KT0 0
#define SM_KT1 (64 * KSTR)
#define SM_V0  (2 * 64 * KSTR)
#define SM_V1  (3 * 64 * KSTR)
#define SM_P   (4 * 64 * KSTR)
#define ATT_SMEM_FLOATS (4 * 64 * KSTR + 64 * PSTR)   // 23296 floats = 93184 B

__global__ __launch_bounds__(128)
void attn_cp_kernel(const float* __restrict__ Q, const float* __restrict__ KT,
                    const float* __restrict__ Vb, float* __restrict__ O)
{
    extern __shared__ float sm[];
    uint32_t smb = (uint32_t)__cvta_generic_to_shared(sm);

    int tid  = threadIdx.x;
    int warp = tid >> 5, lane = tid & 31;
    int gid  = lane >> 2, tg = lane & 3;
    int wq   = warp * 16;

    int bh = blockIdx.y;
    int q0 = blockIdx.x * 64;
    size_t base   = (size_t)(bh >> 4) * SEQ * DM + (bh & 15) * DH;
    size_t ktbase = (size_t)(bh * DH) * SEQ;

    // loader thread mapping
    int lr  = tid >> 4;            // 0..7 (+8 per pass)
    int lc4 = (tid & 15) << 2;     // 0..60

    float* sP = sm + SM_P;

    // ---- stage Q tile (already tf32) into sP, extract fragments
    for (int f = tid; f < 64 * 16; f += 128) {
        int q = f >> 4, c4 = (f & 15) << 2;
        float4 v = *(const float4*)(Q + base + (size_t)(q0 + q) * DM + c4);
        *(float4*)&sP[q * PSTR + c4] = v;
    }
    __syncthreads();

    uint32_t qf[8][4];
    #pragma unroll
    for (int ks = 0; ks < 8; ks++) {
        int k = ks * 8;
        int r0 = (wq + gid) * PSTR, r1 = (wq + gid + 8) * PSTR;
        qf[ks][0] = __float_as_uint(sP[r0 + k + tg]);
        qf[ks][1] = __float_as_uint(sP[r1 + k + tg]);
        qf[ks][2] = __float_as_uint(sP[r0 + k + tg + 4]);
        qf[ks][3] = __float_as_uint(sP[r1 + k + tg + 4]);
    }
    __syncthreads();

    float o[8][4];
    #pragma unroll
    for (int nt = 0; nt < 8; nt++)
        #pragma unroll
        for (int r = 0; r < 4; r++) o[nt][r] = 0.f;
    float m_lo = -INFINITY, m_hi = -INFINITY, l_lo = 0.f, l_hi = 0.f;

    const float scale = 0.125f;   // 1/sqrt(64)
    const int NT = SEQ / 64;

    // ---- prologue: async-load tile 0 into buffer 0
    {
        uint32_t kdst = smb + SM_KT0 * 4;
        uint32_t vdst = smb + SM_V0 * 4;
        const float* ksrc = KT + ktbase;
        const float* vsrc = Vb + base;
        #pragma unroll
        for (int i = 0; i < 8; i++) {
            int r = lr + i * 8;
            cp_async16(kdst + (uint32_t)(r * KSTR + lc4) * 4, ksrc + (size_t)r * SEQ + lc4);
            cp_async16(vdst + (uint32_t)(r * KSTR + lc4) * 4, vsrc + (size_t)r * DM + lc4);
        }
        cp_commit();
    }

    for (int kt = 0; kt < NT; kt++) {
        int cur = kt & 1;
        if (kt + 1 < NT) {
            int k0n = (kt + 1) * 64;
            uint32_t kdst = smb + (cur ? SM_KT0 : SM_KT1) * 4;
            uint32_t vdst = smb + (cur ? SM_V0 : SM_V1) * 4;
            const float* ksrc = KT + ktbase + k0n;
            const float* vsrc = Vb + base + (size_t)k0n * DM;
            #pragma unroll
            for (int i = 0; i < 8; i++) {
                int r = lr + i * 8;
                cp_async16(kdst + (uint32_t)(r * KSTR + lc4) * 4, ksrc + (size_t)r * SEQ + lc4);
                cp_async16(vdst + (uint32_t)(r * KSTR + lc4) * 4, vsrc + (size_t)r * DM + lc4);
            }
            cp_commit();
            cp_wait1();
        } else {
            cp_wait0();
        }
        __syncthreads();

        const float* sKT = sm + (cur ? SM_KT1 : SM_KT0);
        const float* sV  = sm + (cur ? SM_V1 : SM_V0);

        // ---- S = Q @ K^T
        float s[8][4];
        #pragma unroll
        for (int nt = 0; nt < 8; nt++)
            #pragma unroll
            for (int r = 0; r < 4; r++) s[nt][r] = 0.f;

        #pragma unroll
        for (int ks = 0; ks < 8; ks++) {
            uint32_t bf[8][2];
            int kr0 = (ks * 8 + tg) * KSTR;
            int kr1 = (ks * 8 + tg + 4) * KSTR;
            #pragma unroll
            for (int nt = 0; nt < 8; nt++) {
                int cc = nt * 8 + gid;
                bf[nt][0] = __float_as_uint(sKT[kr0 + cc]);
                bf[nt][1] = __float_as_uint(sKT[kr1 + cc]);
            }
            #pragma unroll
            for (int nt = 0; nt < 8; nt++)
                mma_tf32(s[nt], qf[ks][0], qf[ks][1], qf[ks][2], qf[ks][3],
                         bf[nt][0], bf[nt][1]);
        }

        // ---- online softmax (rows: q_lo = wq+gid, q_hi = wq+gid+8)
        float mx_lo = -INFINITY, mx_hi = -INFINITY;
        #pragma unroll
        for (int nt = 0; nt < 8; nt++) {
            s[nt][0] *= scale; s[nt][1] *= scale;
            s[nt][2] *= scale; s[nt][3] *= scale;
            mx_lo = fmaxf(mx_lo, fmaxf(s[nt][0], s[nt][1]));
            mx_hi = fmaxf(mx_hi, fmaxf(s[nt][2], s[nt][3]));
        }
        #pragma unroll
        for (int off = 1; off < 4; off <<= 1) {
            mx_lo = fmaxf(mx_lo, __shfl_xor_sync(0xffffffffu, mx_lo, off));
            mx_hi = fmaxf(mx_hi, __shfl_xor_sync(0xffffffffu, mx_hi, off));
        }
        float mn_lo = fmaxf(m_lo, mx_lo);
        float mn_hi = fmaxf(m_hi, mx_hi);
        float al_lo = __expf(m_lo - mn_lo);
        float al_hi = __expf(m_hi - mn_hi);
        float ps_lo = 0.f, ps_hi = 0.f;
        #pragma unroll
        for (int nt = 0; nt < 8; nt++) {
            s[nt][0] = __expf(s[nt][0] - mn_lo);
            s[nt][1] = __expf(s[nt][1] - mn_lo);
            s[nt][2] = __expf(s[nt][2] - mn_hi);
            s[nt][3] = __expf(s[nt][3] - mn_hi);
            ps_lo += s[nt][0] + s[nt][1];
            ps_hi += s[nt][2] + s[nt][3];
        }
        #pragma unroll
        for (int off = 1; off < 4; off <<= 1) {
            ps_lo += __shfl_xor_sync(0xffffffffu, ps_lo, off);
            ps_hi += __shfl_xor_sync(0xffffffffu, ps_hi, off);
        }
        l_lo = l_lo * al_lo + ps_lo;
        l_hi = l_hi * al_hi + ps_hi;
        m_lo = mn_lo; m_hi = mn_hi;
        #pragma unroll
        for (int nt = 0; nt < 8; nt++) {
            o[nt][0] *= al_lo; o[nt][1] *= al_lo;
            o[nt][2] *= al_hi; o[nt][3] *= al_hi;
        }

        // ---- write P (tf32, RNA) to sP; own warp's rows only -> syncwarp
        #pragma unroll
        for (int nt = 0; nt < 8; nt++) {
            int kc = nt * 8 + 2 * tg;
            float2 p0 = make_float2(to_tf32(s[nt][0]), to_tf32(s[nt][1]));
            float2 p1 = make_float2(to_tf32(s[nt][2]), to_tf32(s[nt][3]));
            *(float2*)&sP[(wq + gid) * PSTR + kc]     = p0;
            *(float2*)&sP[(wq + gid + 8) * PSTR + kc] = p1;
        }
        __syncwarp();

        // ---- O += P @ V
        #pragma unroll
        for (int ks = 0; ks < 8; ks++) {
            uint32_t pa[4], bf[8][2];
            int r0 = (wq + gid) * PSTR, r1 = (wq + gid + 8) * PSTR;
            pa[0] = __float_as_uint(sP[r0 + ks * 8 + tg]);
            pa[1] = __float_as_uint(sP[r1 + ks * 8 + tg]);
            pa[2] = __float_as_uint(sP[r0 + ks * 8 + tg + 4]);
            pa[3] = __float_as_uint(sP[r1 + ks * 8 + tg + 4]);
            int vr0 = (ks * 8 + tg) * KSTR;
            int vr1 = (ks * 8 + tg + 4) * KSTR;
            #pragma unroll
            for (int nt = 0; nt < 8; nt++) {
                int cc = nt * 8 + gid;
                bf[nt][0] = __float_as_uint(sV[vr0 + cc]);
                bf[nt][1] = __float_as_uint(sV[vr1 + cc]);
            }
            #pragma unroll
            for (int nt = 0; nt < 8; nt++)
                mma_tf32(o[nt], pa[0], pa[1], pa[2], pa[3], bf[nt][0], bf[nt][1]);
        }
        __syncthreads();   // compute done before next iter's cp.async overwrites
    }

    // ---- epilogue: normalize and store
    float inv_lo = 1.0f / l_lo;
    float inv_hi = 1.0f / l_hi;
    #pragma unroll
    for (int nt = 0; nt < 8; nt++) {
        int d = nt * 8 + 2 * tg;
        size_t r0 = base + (size_t)(q0 + wq + gid) * DM + d;
        size_t r1 = base + (size_t)(q0 + wq + gid + 8) * DM + d;
        *(float2*)(O + r0) = make_float2(o[nt][0] * inv_lo, o[nt][1] * inv_lo);
        *(float2*)(O + r1) = make_float2(o[nt][2] * inv_hi, o[nt][3] * inv_hi);
    }
}

// ---------------- launcher -------------------------------------------------
extern "C" void kernel_launch(void* const* d_in, const int* in_sizes, int n_in,
                              void* d_out, int out_size)
{
    const float* x      = (const float*)d_in[0];
    const float* Wq     = (const float*)d_in[1];
    const float* bq     = (const float*)d_in[2];
    const float* Wk     = (const float*)d_in[3];
    const float* bk     = (const float*)d_in[4];
    const float* Wv     = (const float*)d_in[5];
    const float* bv     = (const float*)d_in[6];
    const float* Wo     = (const float*)d_in[7];
    const float* bo     = (const float*)d_in[8];
    const float* alpha1 = (const float*)d_in[9];
    const float* beta1  = (const float*)d_in[10];
    const float* alpha2 = (const float*)d_in[11];
    const float* beta2  = (const float*)d_in[12];
    const float* W1     = (const float*)d_in[13];
    const float* b1     = (const float*)d_in[14];
    const float* W2     = (const float*)d_in[15];
    const float* b2     = (const float*)d_in[16];
    float* out = (float*)d_out;

    float *xn, *q, *k, *v, *kt, *ao, *x2, *hn, *h1;
    cudaGetSymbolAddress((void**)&xn, g_xn);
    cudaGetSymbolAddress((void**)&q,  g_q);
    cudaGetSymbolAddress((void**)&k,  g_k);
    cudaGetSymbolAddress((void**)&v,  g_v);
    cudaGetSymbolAddress((void**)&kt, g_kt);
    cudaGetSymbolAddress((void**)&ao, g_ao);
    cudaGetSymbolAddress((void**)&x2, g_x2);
    cudaGetSymbolAddress((void**)&hn, g_hn);
    cudaGetSymbolAddress((void**)&h1, g_h1);

    // 1. x_n = norm1(x)
    norm_kernel<<<ROWS, 256>>>(x, alpha1, beta1, xn);

    // 2. fused Q/K/V projections (outputs tf32-rounded)
    qkv_gemm<<<dim3(24, ROWS / 128), 256>>>(xn, Wq, Wk, Wv, bq, bk, bv, q, k, v);

    // 3. K per-head transpose
    htrans_kernel<<<dim3(SEQ / 64, BATCH * NH), 256>>>(k, kt);

    // 4. attention (cp.async pipelined)
    int att_smem = ATT_SMEM_FLOATS * (int)sizeof(float);   // 93184 B
    cudaFuncSetAttribute(attn_cp_kernel, cudaFuncAttributeMaxDynamicSharedMemorySize, att_smem);
    attn_cp_kernel<<<dim3(SEQ / 64, BATCH * NH), 128, att_smem>>>(q, kt, v, ao);

    // 5. x2 = x_n + ao@Wo + bo
    tgemm<false, true><<<dim3(DM / 128, ROWS / 128), 256>>>(ao, Wo, bo, xn, x2, DM, DM);

    // 6. h_n = norm2(x2)
    norm_kernel<<<ROWS, 256>>>(x2, alpha2, beta2, hn);

    // 7. h1 = relu(h_n@W1 + b1)
    tgemm<true, false><<<dim3(DFF / 128, ROWS / 128), 256>>>(hn, W1, b1, nullptr, h1, DFF, DM);

    // 8. out = x2 + h1@W2 + b2
    tgemm<false, true><<<dim3(DM / 128, ROWS / 128), 256>>>(h1, W2, b2, x2, out, DM, DFF);
}

// round 11
// speedup vs baseline: 1.7833x; 1.2156x over previous
#include <cuda_runtime.h>
#include <cuda_bf16.h>
#include <math.h>
#include <stdint.h>

// Problem constants
#define BATCH 2
#define SEQ   2048
#define DM    1024
#define NH    16
#define DH    64
#define DFF   512
#define ROWS  (BATCH*SEQ)          // 4096

// ---------------- scratch (device globals; no runtime allocation) ----------
__device__ float g_xn[ROWS*DM];    // norm1(x), tf32-rounded
__device__ float g_q [ROWS*DM];    // tf32 Q (pre-scaled by 1/8)
__device__ float g_k [ROWS*DM];    // tf32 K
__device__ float g_v [ROWS*DM];    // tf32 V
__device__ float g_kt[ROWS*DM];    // K transposed per head: [b*16+h][d][s]
__device__ float g_ao[ROWS*DM];    // attention output (tf32)
__device__ float g_x2[ROWS*DM];    // xn + attn@Wo + bo (fp32)
__device__ float g_hn[ROWS*DM];    // norm2(x2), tf32
__device__ float g_h1[ROWS*DFF];   // relu(hn@W1+b1), tf32
// tf32-converted weights
__device__ float g_wq[DM*DM];
__device__ float g_wk[DM*DM];
__device__ float g_wv[DM*DM];
__device__ float g_wo[DM*DM];
__device__ float g_w1[DM*DFF];
__device__ float g_w2[DFF*DM];

// ---------------- helpers ---------------------------------------------------
__device__ __forceinline__ float to_tf32(float x) {
    float r;
    asm("cvt.rna.tf32.f32 %0, %1;" : "=f"(r) : "f"(x));
    return r;
}

__device__ __forceinline__ void mma_tf32(float c[4],
                                         uint32_t a0, uint32_t a1, uint32_t a2, uint32_t a3,
                                         uint32_t b0, uint32_t b1) {
    asm volatile(
        "mma.sync.aligned.m16n8k8.row.col.f32.tf32.tf32.f32 "
        "{%0,%1,%2,%3}, {%4,%5,%6,%7}, {%8,%9}, {%0,%1,%2,%3};"
        : "+f"(c[0]), "+f"(c[1]), "+f"(c[2]), "+f"(c[3])
        : "r"(a0), "r"(a1), "r"(a2), "r"(a3), "r"(b0), "r"(b1));
}

__device__ __forceinline__ void cp_async16(uint32_t sdst, const void* gsrc) {
    asm volatile("cp.async.cg.shared.global [%0], [%1], 16;"
                 :: "r"(sdst), "l"(gsrc) : "memory");
}
__device__ __forceinline__ void cp_commit() {
    asm volatile("cp.async.commit_group;" ::: "memory");
}
__device__ __forceinline__ void cp_wait1() {
    asm volatile("cp.async.wait_group 1;" ::: "memory");
}
__device__ __forceinline__ void cp_wait0() {
    asm volatile("cp.async.wait_group 0;" ::: "memory");
}

// ---------------- weight tf32 pre-conversion --------------------------------
__global__ __launch_bounds__(256)
void wcvt_kernel(const float* __restrict__ S, float* __restrict__ D, int n4)
{
    int i = blockIdx.x * 256 + threadIdx.x;
    if (i < n4) {
        float4 v = ((const float4*)S)[i];
        v.x = to_tf32(v.x); v.y = to_tf32(v.y);
        v.z = to_tf32(v.z); v.w = to_tf32(v.w);
        ((float4*)D)[i] = v;
    }
}

// ---------------- NormLayer (output optionally tf32-rounded) ---------------
template<bool CVT>
__global__ __launch_bounds__(256)
void norm_kernel(const float* __restrict__ X,
                 const float* __restrict__ alpha,
                 const float* __restrict__ beta,
                 float* __restrict__ Y)
{
    int row = blockIdx.x;
    int tid = threadIdx.x;
    const float* xr = X + (size_t)row * DM;

    float4 v = *(const float4*)(xr + tid * 4);
    float s  = v.x + v.y + v.z + v.w;
    float sq = v.x*v.x + v.y*v.y + v.z*v.z + v.w*v.w;

    #pragma unroll
    for (int m = 16; m; m >>= 1) {
        s  += __shfl_xor_sync(0xffffffffu, s,  m);
        sq += __shfl_xor_sync(0xffffffffu, sq, m);
    }
    __shared__ float red[16];
    __shared__ float s_mean, s_rstd;
    int wid  = tid >> 5;
    int lane = tid & 31;
    if (lane == 0) { red[wid] = s; red[8 + wid] = sq; }
    __syncthreads();
    if (tid == 0) {
        float S = 0.f, SQ = 0.f;
        #pragma unroll
        for (int w = 0; w < 8; w++) { S += red[w]; SQ += red[8 + w]; }
        float mean = S * (1.0f / DM);
        float var  = (SQ - (float)DM * mean * mean) * (1.0f / (DM - 1));
        s_mean = mean;
        s_rstd = rsqrtf(var + 1e-6f);
    }
    __syncthreads();
    float mean = s_mean, rstd = s_rstd;

    float4 a = *(const float4*)(alpha + tid * 4);
    float4 b = *(const float4*)(beta  + tid * 4);
    float4 o;
    o.x = a.x * (v.x - mean) * rstd + b.x;
    o.y = a.y * (v.y - mean) * rstd + b.y;
    o.z = a.z * (v.z - mean) * rstd + b.z;
    o.w = a.w * (v.w - mean) * rstd + b.w;
    if (CVT) {
        o.x = to_tf32(o.x); o.y = to_tf32(o.y);
        o.z = to_tf32(o.z); o.w = to_tf32(o.w);
    }
    *(float4*)(Y + (size_t)row * DM + tid * 4) = o;
}

// ---------------- per-head transpose: X[row][h*64+d] -> XT[bh][d][s] --------
__global__ __launch_bounds__(256)
void htrans_kernel(const float* __restrict__ X, float* __restrict__ XT)
{
    __shared__ float ts[64 * 65];
    int tid = threadIdx.x;
    int bh = blockIdx.y;
    int s0 = blockIdx.x * 64;
    size_t base = (size_t)(bh >> 4) * SEQ * DM + (bh & 15) * DH;

    for (int f = tid; f < 64 * 16; f += 256) {
        int s = f >> 4, c4 = (f & 15) << 2;
        float4 v = *(const float4*)(X + base + (size_t)(s0 + s) * DM + c4);
        ts[s * 65 + c4 + 0] = v.x;
        ts[s * 65 + c4 + 1] = v.y;
        ts[s * 65 + c4 + 2] = v.z;
        ts[s * 65 + c4 + 3] = v.w;
    }
    __syncthreads();
    for (int f = tid; f < 64 * 16; f += 256) {
        int d = f >> 4, s4 = (f & 15) << 2;
        float4 w;
        w.x = ts[(s4 + 0) * 65 + d];
        w.y = ts[(s4 + 1) * 65 + d];
        w.z = ts[(s4 + 2) * 65 + d];
        w.w = ts[(s4 + 3) * 65 + d];
        *(float4*)(XT + (size_t)(bh * DH + d) * SEQ + s0 + s4) = w;
    }
}

// ---------------- tgemm3: 128x128 block, 4 warps (64x64), cp.async ---------
// All inputs pre-rounded tf32 -> raw cp.async, no cvt in mainloop.
// sA [m][k] stride 20, sB [k][n] stride 136, both double-buffered.
#define GA_STR 20
#define GB_STR 136
#define G_SA0 0
#define G_SA1 (128 * GA_STR)                    // 2560
#define G_SB0 (2 * 128 * GA_STR)                // 5120
#define G_SB1 (G_SB0 + 16 * GB_STR)             // 7296
#define G_SMEM (G_SB0 + 2 * 16 * GB_STR)        // 9472 floats = 37888 B

template<bool RELU, bool HAS_RES, bool CVT_OUT>
__device__ __forceinline__ void gemm3_body(
    const float* __restrict__ A, const float* __restrict__ B,
    const float* __restrict__ bias, const float* __restrict__ Res,
    float* __restrict__ C, int N, int K, int bm, int bn, float outscale)
{
    __shared__ float sm[G_SMEM];
    uint32_t smb = (uint32_t)__cvta_generic_to_shared(sm);

    int tid  = threadIdx.x;
    int warp = tid >> 5, lane = tid & 31;
    int gid  = lane >> 2, tg = lane & 3;
    int wm   = (warp & 1) * 64;
    int wn   = (warp >> 1) * 64;

    int am[4], ac4[4], bk[4], bn4[4];
    #pragma unroll
    for (int i = 0; i < 4; i++) {
        int f = tid + 128 * i;
        am[i]  = f >> 2;            // 0..127
        ac4[i] = (f & 3) << 2;      // 0,4,8,12
        bk[i]  = f >> 5;            // 0..15
        bn4[i] = (f & 31) << 2;     // 0..124
    }
    const float* Ab = A + (size_t)(bm * 128) * K;
    const float* Bb = B + bn * 128;

    int nk = K >> 4;

    // prologue: chunk 0 -> buf 0
    #pragma unroll
    for (int i = 0; i < 4; i++) {
        cp_async16(smb + (uint32_t)(G_SA0 + am[i] * GA_STR + ac4[i]) * 4,
                   Ab + (size_t)am[i] * K + ac4[i]);
        cp_async16(smb + (uint32_t)(G_SB0 + bk[i] * GB_STR + bn4[i]) * 4,
                   Bb + (size_t)bk[i] * N + bn4[i]);
    }
    cp_commit();

    float acc[4][8][4];
    #pragma unroll
    for (int mt = 0; mt < 4; mt++)
        #pragma unroll
        for (int nt = 0; nt < 8; nt++)
            #pragma unroll
            for (int r = 0; r < 4; r++) acc[mt][nt][r] = 0.f;

    for (int kt = 0; kt < nk; kt++) {
        int cur = kt & 1;
        if (kt + 1 < nk) {
            int k0 = (kt + 1) << 4;
            uint32_t sa = cur ? G_SA0 : G_SA1;
            uint32_t sb = cur ? G_SB0 : G_SB1;
            #pragma unroll
            for (int i = 0; i < 4; i++) {
                cp_async16(smb + (sa + am[i] * GA_STR + ac4[i]) * 4,
                           Ab + (size_t)am[i] * K + k0 + ac4[i]);
                cp_async16(smb + (sb + bk[i] * GB_STR + bn4[i]) * 4,
                           Bb + (size_t)(k0 + bk[i]) * N + bn4[i]);
            }
            cp_commit();
            cp_wait1();
        } else {
            cp_wait0();
        }
        __syncthreads();

        const float* As = sm + (cur ? G_SA1 : G_SA0);
        const float* Bs = sm + (cur ? G_SB1 : G_SB0);
        #pragma unroll
        for (int kk = 0; kk < 16; kk += 8) {
            uint32_t af[4][4], bf[8][2];
            #pragma unroll
            for (int mt = 0; mt < 4; mt++) {
                int r0 = (wm + mt * 16 + gid) * GA_STR;
                int r1 = (wm + mt * 16 + gid + 8) * GA_STR;
                af[mt][0] = __float_as_uint(As[r0 + kk + tg]);
                af[mt][1] = __float_as_uint(As[r1 + kk + tg]);
                af[mt][2] = __float_as_uint(As[r0 + kk + tg + 4]);
                af[mt][3] = __float_as_uint(As[r1 + kk + tg + 4]);
            }
            #pragma unroll
            for (int nt = 0; nt < 8; nt++) {
                int cc = wn + nt * 8 + gid;
                bf[nt][0] = __float_as_uint(Bs[(kk + tg) * GB_STR + cc]);
                bf[nt][1] = __float_as_uint(Bs[(kk + tg + 4) * GB_STR + cc]);
            }
            #pragma unroll
            for (int mt = 0; mt < 4; mt++)
                #pragma unroll
                for (int nt = 0; nt < 8; nt++)
                    mma_tf32(acc[mt][nt], af[mt][0], af[mt][1], af[mt][2], af[mt][3],
                             bf[nt][0], bf[nt][1]);
        }
        __syncthreads();
    }

    #pragma unroll
    for (int nt = 0; nt < 8; nt++) {
        int col = bn * 128 + wn + nt * 8 + 2 * tg;
        float2 bv = *(const float2*)(bias + col);
        #pragma unroll
        for (int mt = 0; mt < 4; mt++) {
            int r0 = bm * 128 + wm + mt * 16 + gid;
            int r1 = r0 + 8;
            float2 c0 = make_float2(acc[mt][nt][0] + bv.x, acc[mt][nt][1] + bv.y);
            float2 c1 = make_float2(acc[mt][nt][2] + bv.x, acc[mt][nt][3] + bv.y);
            if (RELU) {
                c0.x = fmaxf(c0.x, 0.f); c0.y = fmaxf(c0.y, 0.f);
                c1.x = fmaxf(c1.x, 0.f); c1.y = fmaxf(c1.y, 0.f);
            }
            if (HAS_RES) {
                float2 r0v = *(const float2*)(Res + (size_t)r0 * N + col);
                float2 r1v = *(const float2*)(Res + (size_t)r1 * N + col);
                c0.x += r0v.x; c0.y += r0v.y;
                c1.x += r1v.x; c1.y += r1v.y;
            }
            if (CVT_OUT) {
                c0.x = to_tf32(c0.x * outscale); c0.y = to_tf32(c0.y * outscale);
                c1.x = to_tf32(c1.x * outscale); c1.y = to_tf32(c1.y * outscale);
            }
            *(float2*)(C + (size_t)r0 * N + col) = c0;
            *(float2*)(C + (size_t)r1 * N + col) = c1;
        }
    }
}

template<bool RELU, bool HAS_RES, bool CVT_OUT>
__global__ __launch_bounds__(128)
void tgemm3(const float* __restrict__ A, const float* __restrict__ B,
            const float* __restrict__ bias, const float* __restrict__ Res,
            float* __restrict__ C, int N, int K)
{
    gemm3_body<RELU, HAS_RES, CVT_OUT>(A, B, bias, Res, C, N, K,
                                       blockIdx.y, blockIdx.x, 1.0f);
}

// fused QKV: blockIdx.x 0..23 -> sel = x>>3, col block = x&7.
// Q output pre-scaled by 1/8 (attention softmax scale folded in).
__global__ __launch_bounds__(128)
void qkv_gemm3(const float* __restrict__ A,
               const float* __restrict__ Wq, const float* __restrict__ Wk,
               const float* __restrict__ Wv,
               const float* __restrict__ bq, const float* __restrict__ bk,
               const float* __restrict__ bv,
               float* __restrict__ Oq, float* __restrict__ Ok, float* __restrict__ Ov)
{
    int sel = blockIdx.x >> 3;
    int bn  = blockIdx.x & 7;
    const float* B    = (sel == 0) ? Wq : (sel == 1) ? Wk : Wv;
    const float* bias = (sel == 0) ? bq : (sel == 1) ? bk : bv;
    float* C          = (sel == 0) ? Oq : (sel == 1) ? Ok : Ov;
    float outscale    = (sel == 0) ? 0.125f : 1.0f;
    gemm3_body<false, false, true>(A, B, bias, nullptr, C, DM, DM,
                                   blockIdx.y, bn, outscale);
}

// ---------------- flash attention: cp.async + P aliased into K buffer ------
// 128 threads (4 warps), 64 queries/block, 64-key tiles.
// smem = 2x(KT 64x72) + 2x(V 64x72) = 73728 B -> 3 blocks/SM.
// After S-mma, sKT[cur] is dead; P is written there with XOR-4 swizzle
// (conflict-free loads full-warp; stores conflict-free per 64-bit phase).
#define KSTR 72
#define SM_KT0 0
#define SM_KT1 (64 * KSTR)
#define SM_V0  (2 * 64 * KSTR)
#define SM_V1  (3 * 64 * KSTR)
#define ATT_SMEM_FLOATS (4 * 64 * KSTR)   // 18432 floats = 73728 B

__global__ __launch_bounds__(128)
void attn3_kernel(const float* __restrict__ Q, const float* __restrict__ KT,
                  const float* __restrict__ Vb, float* __restrict__ O)
{
    extern __shared__ float sm[];
    uint32_t smb = (uint32_t)__cvta_generic_to_shared(sm);

    int tid  = threadIdx.x;
    int warp = tid >> 5, lane = tid & 31;
    int gid  = lane >> 2, tg = lane & 3;
    int wq   = warp * 16;
    int b4   = ((gid >> 2) & 1) << 2;   // P swizzle bit

    int bh = blockIdx.y;
    int q0 = blockIdx.x * 64;
    size_t base   = (size_t)(bh >> 4) * SEQ * DM + (bh & 15) * DH;
    size_t ktbase = (size_t)(bh * DH) * SEQ;

    int lr  = tid >> 4;            // 0..7
    int lc4 = (tid & 15) << 2;     // 0..60

    // ---- stage Q (tf32, pre-scaled) at stride 76 in KT region, extract frags
    for (int f = tid; f < 64 * 16; f += 128) {
        int q = f >> 4, c4 = (f & 15) << 2;
        float4 v = *(const float4*)(Q + base + (size_t)(q0 + q) * DM + c4);
        *(float4*)&sm[q * 76 + c4] = v;
    }
    __syncthreads();

    uint32_t qf[8][4];
    #pragma unroll
    for (int ks = 0; ks < 8; ks++) {
        int k = ks * 8;
        int r0 = (wq + gid) * 76, r1 = (wq + gid + 8) * 76;
        qf[ks][0] = __float_as_uint(sm[r0 + k + tg]);
        qf[ks][1] = __float_as_uint(sm[r1 + k + tg]);
        qf[ks][2] = __float_as_uint(sm[r0 + k + tg + 4]);
        qf[ks][3] = __float_as_uint(sm[r1 + k + tg + 4]);
    }
    __syncthreads();

    float o[8][4];
    #pragma unroll
    for (int nt = 0; nt < 8; nt++)
        #pragma unroll
        for (int r = 0; r < 4; r++) o[nt][r] = 0.f;
    float m_lo = -INFINITY, m_hi = -INFINITY, l_lo = 0.f, l_hi = 0.f;

    const int NT = SEQ / 64;

    // ---- prologue: async-load tile 0 into buffer 0
    {
        uint32_t kdst = smb + SM_KT0 * 4;
        uint32_t vdst = smb + SM_V0 * 4;
        const float* ksrc = KT + ktbase;
        const float* vsrc = Vb + base;
        #pragma unroll
        for (int i = 0; i < 8; i++) {
            int r = lr + i * 8;
            cp_async16(kdst + (uint32_t)(r * KSTR + lc4) * 4, ksrc + (size_t)r * SEQ + lc4);
            cp_async16(vdst + (uint32_t)(r * KSTR + lc4) * 4, vsrc + (size_t)r * DM + lc4);
        }
        cp_commit();
    }

    for (int kt = 0; kt < NT; kt++) {
        int cur = kt & 1;
        if (kt + 1 < NT) {
            int k0n = (kt + 1) * 64;
            uint32_t kdst = smb + (cur ? SM_KT0 : SM_KT1) * 4;
            uint32_t vdst = smb + (cur ? SM_V0 : SM_V1) * 4;
            const float* ksrc = KT + ktbase + k0n;
            const float* vsrc = Vb + base + (size_t)k0n * DM;
            #pragma unroll
            for (int i = 0; i < 8; i++) {
                int r = lr + i * 8;
                cp_async16(kdst + (uint32_t)(r * KSTR + lc4) * 4, ksrc + (size_t)r * SEQ + lc4);
                cp_async16(vdst + (uint32_t)(r * KSTR + lc4) * 4, vsrc + (size_t)r * DM + lc4);
            }
            cp_commit();
            cp_wait1();
        } else {
            cp_wait0();
        }
        __syncthreads();

        float* sKT = sm + (cur ? SM_KT1 : SM_KT0);
        const float* sV = sm + (cur ? SM_V1 : SM_V0);

        // ---- S = Q @ K^T  (Q pre-scaled by 1/8)
        float s[8][4];
        #pragma unroll
        for (int nt = 0; nt < 8; nt++)
            #pragma unroll
            for (int r = 0; r < 4; r++) s[nt][r] = 0.f;

        #pragma unroll
        for (int ks = 0; ks < 8; ks++) {
            uint32_t bf[8][2];
            int kr0 = (ks * 8 + tg) * KSTR;
            int kr1 = (ks * 8 + tg + 4) * KSTR;
            #pragma unroll
            for (int nt = 0; nt < 8; nt++) {
                int cc = nt * 8 + gid;
                bf[nt][0] = __float_as_uint(sKT[kr0 + cc]);
                bf[nt][1] = __float_as_uint(sKT[kr1 + cc]);
            }
            #pragma unroll
            for (int nt = 0; nt < 8; nt++)
                mma_tf32(s[nt], qf[ks][0], qf[ks][1], qf[ks][2], qf[ks][3],
                         bf[nt][0], bf[nt][1]);
        }

        // ---- online softmax
        float mx_lo = -INFINITY, mx_hi = -INFINITY;
        #pragma unroll
        for (int nt = 0; nt < 8; nt++) {
            mx_lo = fmaxf(mx_lo, fmaxf(s[nt][0], s[nt][1]));
            mx_hi = fmaxf(mx_hi, fmaxf(s[nt][2], s[nt][3]));
        }
        #pragma unroll
        for (int off = 1; off < 4; off <<= 1) {
            mx_lo = fmaxf(mx_lo, __shfl_xor_sync(0xffffffffu, mx_lo, off));
            mx_hi = fmaxf(mx_hi, __shfl_xor_sync(0xffffffffu, mx_hi, off));
        }
        float mn_lo = fmaxf(m_lo, mx_lo);
        float mn_hi = fmaxf(m_hi, mx_hi);
        float al_lo = __expf(m_lo - mn_lo);
        float al_hi = __expf(m_hi - mn_hi);
        float ps_lo = 0.f, ps_hi = 0.f;
        #pragma unroll
        for (int nt = 0; nt < 8; nt++) {
            s[nt][0] = __expf(s[nt][0] - mn_lo);
            s[nt][1] = __expf(s[nt][1] - mn_lo);
            s[nt][2] = __expf(s[nt][2] - mn_hi);
            s[nt][3] = __expf(s[nt][3] - mn_hi);
            ps_lo += s[nt][0] + s[nt][1];
            ps_hi += s[nt][2] + s[nt][3];
        }
        #pragma unroll
        for (int off = 1; off < 4; off <<= 1) {
            ps_lo += __shfl_xor_sync(0xffffffffu, ps_lo, off);
            ps_hi += __shfl_xor_sync(0xffffffffu, ps_hi, off);
        }
        l_lo = l_lo * al_lo + ps_lo;
        l_hi = l_hi * al_hi + ps_hi;
        m_lo = mn_lo; m_hi = mn_hi;
        #pragma unroll
        for (int nt = 0; nt < 8; nt++) {
            o[nt][0] *= al_lo; o[nt][1] *= al_lo;
            o[nt][2] *= al_hi; o[nt][3] *= al_hi;
        }

        // ---- all warps done reading sKT[cur]; reuse it for P
        __syncthreads();

        #pragma unroll
        for (int nt = 0; nt < 8; nt++) {
            int kc = nt * 8 + ((2 * tg) ^ b4);
            float2 p0 = make_float2(to_tf32(s[nt][0]), to_tf32(s[nt][1]));
            float2 p1 = make_float2(to_tf32(s[nt][2]), to_tf32(s[nt][3]));
            *(float2*)&sKT[(wq + gid) * KSTR + kc]     = p0;
            *(float2*)&sKT[(wq + gid + 8) * KSTR + kc] = p1;
        }
        __syncwarp();

        // ---- O += P @ V
        #pragma unroll
        for (int ks = 0; ks < 8; ks++) {
            uint32_t pa[4], bf[8][2];
            int r0 = (wq + gid) * KSTR, r1 = (wq + gid + 8) * KSTR;
            int klo = ks * 8 + (tg ^ b4);
            int khi = ks * 8 + ((tg + 4) ^ b4);
            pa[0] = __float_as_uint(sKT[r0 + klo]);
            pa[1] = __float_as_uint(sKT[r1 + klo]);
            pa[2] = __float_as_uint(sKT[r0 + khi]);
            pa[3] = __float_as_uint(sKT[r1 + khi]);
            int vr0 = (ks * 8 + tg) * KSTR;
            int vr1 = (ks * 8 + tg + 4) * KSTR;
            #pragma unroll
            for (int nt = 0; nt < 8; nt++) {
                int cc = nt * 8 + gid;
                bf[nt][0] = __float_as_uint(sV[vr0 + cc]);
                bf[nt][1] = __float_as_uint(sV[vr1 + cc]);
            }
            #pragma unroll
            for (int nt = 0; nt < 8; nt++)
                mma_tf32(o[nt], pa[0], pa[1], pa[2], pa[3], bf[nt][0], bf[nt][1]);
        }
        __syncthreads();   // compute done before next iter's cp.async overwrites
    }

    // ---- epilogue: normalize, tf32-round, store
    float inv_lo = 1.0f / l_lo;
    float inv_hi = 1.0f / l_hi;
    #pragma unroll
    for (int nt = 0; nt < 8; nt++) {
        int d = nt * 8 + 2 * tg;
        size_t r0 = base + (size_t)(q0 + wq + gid) * DM + d;
        size_t r1 = base + (size_t)(q0 + wq + gid + 8) * DM + d;
        *(float2*)(O + r0) = make_float2(to_tf32(o[nt][0] * inv_lo), to_tf32(o[nt][1] * inv_lo));
        *(float2*)(O + r1) = make_float2(to_tf32(o[nt][2] * inv_hi), to_tf32(o[nt][3] * inv_hi));
    }
}

// ---------------- launcher -------------------------------------------------
extern "C" void kernel_launch(void* const* d_in, const int* in_sizes, int n_in,
                              void* d_out, int out_size)
{
    const float* x      = (const float*)d_in[0];
    const float* Wq     = (const float*)d_in[1];
    const float* bq     = (const float*)d_in[2];
    const float* Wk     = (const float*)d_in[3];
    const float* bk     = (const float*)d_in[4];
    const float* Wv     = (const float*)d_in[5];
    const float* bv     = (const float*)d_in[6];
    const float* Wo     = (const float*)d_in[7];
    const float* bo     = (const float*)d_in[8];
    const float* alpha1 = (const float*)d_in[9];
    const float* beta1  = (const float*)d_in[10];
    const float* alpha2 = (const float*)d_in[11];
    const float* beta2  = (const float*)d_in[12];
    const float* W1     = (const float*)d_in[13];
    const float* b1     = (const float*)d_in[14];
    const float* W2     = (const float*)d_in[15];
    const float* b2     = (const float*)d_in[16];
    float* out = (float*)d_out;

    float *xn, *q, *k, *v, *kt, *ao, *x2, *hn, *h1;
    float *wq, *wk, *wv, *wo, *w1, *w2;
    cudaGetSymbolAddress((void**)&xn, g_xn);
    cudaGetSymbolAddress((void**)&q,  g_q);
    cudaGetSymbolAddress((void**)&k,  g_k);
    cudaGetSymbolAddress((void**)&v,  g_v);
    cudaGetSymbolAddress((void**)&kt, g_kt);
    cudaGetSymbolAddress((void**)&ao, g_ao);
    cudaGetSymbolAddress((void**)&x2, g_x2);
    cudaGetSymbolAddress((void**)&hn, g_hn);
    cudaGetSymbolAddress((void**)&h1, g_h1);
    cudaGetSymbolAddress((void**)&wq, g_wq);
    cudaGetSymbolAddress((void**)&wk, g_wk);
    cudaGetSymbolAddress((void**)&wv, g_wv);
    cudaGetSymbolAddress((void**)&wo, g_wo);
    cudaGetSymbolAddress((void**)&w1, g_w1);
    cudaGetSymbolAddress((void**)&w2, g_w2);

    // 0. pre-convert weights to tf32
    wcvt_kernel<<<DM * DM / 4 / 256, 256>>>(Wq, wq, DM * DM / 4);
    wcvt_kernel<<<DM * DM / 4 / 256, 256>>>(Wk, wk, DM * DM / 4);
    wcvt_kernel<<<DM * DM / 4 / 256, 256>>>(Wv, wv, DM * DM / 4);
    wcvt_kernel<<<DM * DM / 4 / 256, 256>>>(Wo, wo, DM * DM / 4);
    wcvt_kernel<<<DM * DFF / 4 / 256, 256>>>(W1, w1, DM * DFF / 4);
    wcvt_kernel<<<DFF * DM / 4 / 256, 256>>>(W2, w2, DFF * DM / 4);

    // 1. x_n = norm1(x), tf32
    norm_kernel<true><<<ROWS, 256>>>(x, alpha1, beta1, xn);

    // 2. fused Q/K/V projections (tf32 out; Q pre-scaled by 1/8)
    qkv_gemm3<<<dim3(24, ROWS / 128), 128>>>(xn, wq, wk, wv, bq, bk, bv, q, k, v);

    // 3. K per-head transpose
    htrans_kernel<<<dim3(SEQ / 64, BATCH * NH), 256>>>(k, kt);

    // 4. attention (3 blocks/SM)
    int att_smem = ATT_SMEM_FLOATS * (int)sizeof(float);   // 73728 B
    cudaFuncSetAttribute(attn3_kernel, cudaFuncAttributeMaxDynamicSharedMemorySize, att_smem);
    attn3_kernel<<<dim3(SEQ / 64, BATCH * NH), 128, att_smem>>>(q, kt, v, ao);

    // 5. x2 = x_n + ao@Wo + bo (fp32 out)
    tgemm3<false, true, false><<<dim3(DM / 128, ROWS / 128), 128>>>(ao, wo, bo, xn, x2, DM, DM);

    // 6. h_n = norm2(x2), tf32
    norm_kernel<true><<<ROWS, 256>>>(x2, alpha2, beta2, hn);

    // 7. h1 = relu(h_n@W1 + b1), tf32
    tgemm3<true, false, true><<<dim3(DFF / 128, ROWS / 128), 128>>>(hn, w1, b1, nullptr, h1, DFF, DM);

    // 8. out = x2 + h1@W2 + b2 (fp32)
    tgemm3<false, true, false><<<dim3(DM / 128, ROWS / 128), 128>>>(h1, w2, b2, x2, out, DM, DFF);
}